// round 9
// baseline (speedup 1.0000x reference)
#include <cuda_runtime.h>

#define NT      250000
#define NNODES  20000
#define EMB     64
#define NC      16
#define NRP     (NNODES*8)

// ---------------- scratch ---------------------------------------------------
__device__ __align__(16) float g_l1[NT*8];       // raw l1
__device__ __align__(16) float g_l2[NT*8];       // softmaxed l2
__device__ float g_colsum[NRP];
__device__ float g_rowsum[NRP];
__device__ __align__(16) float g_invC[NRP];      // [o][p] = 1/colsum[o*p]
__device__ __align__(16) float g_invR[NRP];      // [s][p] = 1/max(rowsum[s*p],1e-6)
__device__ __align__(16) float g_h[NNODES*EMB];
__device__ int   g_cnt_s[NNODES];
__device__ int   g_off_s[NNODES+1];
__device__ int   g_cur_s[NNODES];
__device__ int   g_perm_s[NT];
__device__ float g_out0[64*16];                  // striped partials for p=0 logits

// ---------------- K0: zero + init logits + s-histogram ----------------------
__global__ void k0_init(float* __restrict__ out, const float* __restrict__ bias2,
                        const int* __restrict__ hrow) {
    int i = blockIdx.x * blockDim.x + threadIdx.x;
    int stride = gridDim.x * blockDim.x;
    for (int j = i; j < NNODES; j += stride) g_cnt_s[j] = 0;
    for (int j = i; j < NRP; j += stride) { g_colsum[j] = 0.f; g_rowsum[j] = 0.f; }
    for (int j = i; j < NNODES*NC; j += stride) out[j] = bias2[j & (NC-1)];
    for (int j = i; j < 64*16; j += stride) g_out0[j] = 0.f;
    __threadfence();   // cnt zeroing visible before histogram within this grid
    __syncthreads();
    for (int t = i; t < NT; t += stride) atomicAdd(&g_cnt_s[hrow[t]], 1);
}

// ---------------- K3: fast 3-level shuffle scan (1 block) -------------------
__global__ __launch_bounds__(1024) void k3_scan() {
    int tid = threadIdx.x;
    const int CH = 20;
    int base = tid * CH;
    int loc[CH]; int sum = 0;
#pragma unroll
    for (int j = 0; j < CH; j++) {
        int idx = base + j;
        int v = (idx < NNODES) ? g_cnt_s[idx] : 0;
        loc[j] = v; sum += v;
    }
    int lane = tid & 31, wid = tid >> 5;
    int x = sum;
#pragma unroll
    for (int d = 1; d < 32; d <<= 1) {
        int y = __shfl_up_sync(0xffffffffu, x, d);
        if (lane >= d) x += y;
    }
    __shared__ int wsum[32];
    if (lane == 31) wsum[wid] = x;
    __syncthreads();
    if (wid == 0) {
        int w = wsum[lane];
#pragma unroll
        for (int d = 1; d < 32; d <<= 1) {
            int y = __shfl_up_sync(0xffffffffu, w, d);
            if (lane >= d) w += y;
        }
        wsum[lane] = w;
    }
    __syncthreads();
    int run = x - sum + (wid ? wsum[wid - 1] : 0);
#pragma unroll
    for (int j = 0; j < CH; j++) {
        int idx = base + j;
        if (idx < NNODES) { g_off_s[idx] = run; g_cur_s[idx] = run; run += loc[j]; }
    }
    if (tid == 1023) g_off_s[NNODES] = wsum[31];
}

// ---------------- K4: scatter edge ids into CSR -----------------------------
__global__ void k4_scatter(const int* __restrict__ hrow) {
    int i = blockIdx.x * blockDim.x + threadIdx.x;
    int stride = gridDim.x * blockDim.x;
    for (int t = i; t < NT; t += stride) {
        int p = atomicAdd(&g_cur_s[hrow[t]], 1);
        g_perm_s[p] = t;
    }
}

// ---------------- K1: GEMMs + softmax + colsum/rowsum atomics ----------------
// (profiled slot: launch index 3)
__global__ __launch_bounds__(256) void k1_l1l2(
    const float* __restrict__ rm,
    const float* __restrict__ Wl1, const float* __restrict__ bl1,
    const float* __restrict__ Wl2, const float* __restrict__ bl2,
    const int* __restrict__ hrow, const int* __restrict__ vcol)
{
    __shared__ float4 sW14[128], sW24[128];
    __shared__ float sb1[8], sb2[8];
    int tid = threadIdx.x;
    if (tid < 128) { sW14[tid] = ((const float4*)Wl1)[tid]; sW24[tid] = ((const float4*)Wl2)[tid]; }
    if (tid < 8) { sb1[tid] = bl1[tid]; sb2[tid] = bl2[tid]; }
    __syncthreads();

    const float4* rm4 = (const float4*)rm;
    int r0 = blockIdx.x * 512 + tid;

    float a1[2][8], a2[2][8];
#pragma unroll
    for (int rr = 0; rr < 2; rr++)
#pragma unroll
        for (int p = 0; p < 8; p++) { a1[rr][p] = sb1[p]; a2[rr][p] = sb2[p]; }

    for (int k4 = 0; k4 < 16; k4++) {
        float4 x[2];
#pragma unroll
        for (int rr = 0; rr < 2; rr++) {
            int row = r0 + rr * 256;
            x[rr] = (row < NT) ? rm4[(size_t)row * 16 + k4] : make_float4(0.f,0.f,0.f,0.f);
        }
#pragma unroll
        for (int j = 0; j < 4; j++) {
            int k = k4 * 4 + j;
            float4 w1lo = sW14[k*2], w1hi = sW14[k*2+1];
            float4 w2lo = sW24[k*2], w2hi = sW24[k*2+1];
#pragma unroll
            for (int rr = 0; rr < 2; rr++) {
                float xv = (j == 0) ? x[rr].x : (j == 1) ? x[rr].y : (j == 2) ? x[rr].z : x[rr].w;
                a1[rr][0] = fmaf(xv, w1lo.x, a1[rr][0]);
                a1[rr][1] = fmaf(xv, w1lo.y, a1[rr][1]);
                a1[rr][2] = fmaf(xv, w1lo.z, a1[rr][2]);
                a1[rr][3] = fmaf(xv, w1lo.w, a1[rr][3]);
                a1[rr][4] = fmaf(xv, w1hi.x, a1[rr][4]);
                a1[rr][5] = fmaf(xv, w1hi.y, a1[rr][5]);
                a1[rr][6] = fmaf(xv, w1hi.z, a1[rr][6]);
                a1[rr][7] = fmaf(xv, w1hi.w, a1[rr][7]);
                a2[rr][0] = fmaf(xv, w2lo.x, a2[rr][0]);
                a2[rr][1] = fmaf(xv, w2lo.y, a2[rr][1]);
                a2[rr][2] = fmaf(xv, w2lo.z, a2[rr][2]);
                a2[rr][3] = fmaf(xv, w2lo.w, a2[rr][3]);
                a2[rr][4] = fmaf(xv, w2hi.x, a2[rr][4]);
                a2[rr][5] = fmaf(xv, w2hi.y, a2[rr][5]);
                a2[rr][6] = fmaf(xv, w2hi.z, a2[rr][6]);
                a2[rr][7] = fmaf(xv, w2hi.w, a2[rr][7]);
            }
        }
    }

    float p0l1 = 0.f, p0l2 = 0.f;
#pragma unroll
    for (int rr = 0; rr < 2; rr++) {
        int row = r0 + rr * 256;
        if (row >= NT) continue;
        float m = a2[rr][0];
#pragma unroll
        for (int p = 1; p < 8; p++) m = fmaxf(m, a2[rr][p]);
        float e[8], ssum = 0.f;
#pragma unroll
        for (int p = 0; p < 8; p++) { e[p] = __expf(a2[rr][p] - m); ssum += e[p]; }
        float inv = 1.f / ssum;
#pragma unroll
        for (int p = 0; p < 8; p++) e[p] *= inv;

        float4* d1 = (float4*)(g_l1 + (size_t)row * 8);
        float4* d2 = (float4*)(g_l2 + (size_t)row * 8);
        d1[0] = make_float4(a1[rr][0], a1[rr][1], a1[rr][2], a1[rr][3]);
        d1[1] = make_float4(a1[rr][4], a1[rr][5], a1[rr][6], a1[rr][7]);
        d2[0] = make_float4(e[0], e[1], e[2], e[3]);
        d2[1] = make_float4(e[4], e[5], e[6], e[7]);

        int o = vcol[row], s = hrow[row];
        p0l1 += a1[rr][0];
        p0l2 += e[0];
#pragma unroll
        for (int p = 1; p < 8; p++) {
            atomicAdd(&g_colsum[o * p], a1[rr][p]);
            atomicAdd(&g_rowsum[s * p], e[p]);
        }
    }

    int lane = tid & 31, wid = tid >> 5;
#pragma unroll
    for (int d = 16; d > 0; d >>= 1) {
        p0l1 += __shfl_down_sync(0xffffffffu, p0l1, d);
        p0l2 += __shfl_down_sync(0xffffffffu, p0l2, d);
    }
    __shared__ float red1[8], red2[8];
    if (lane == 0) { red1[wid] = p0l1; red2[wid] = p0l2; }
    __syncthreads();
    if (tid == 0) {
        float s1 = 0.f, s2 = 0.f;
#pragma unroll
        for (int w = 0; w < 8; w++) { s1 += red1[w]; s2 += red2[w]; }
        atomicAdd(&g_colsum[0], s1);
        atomicAdd(&g_rowsum[0], s2);
    }
}

// ---------------- Kinv: build inverse tables --------------------------------
__global__ void kinv_tables() {
    int i = blockIdx.x * blockDim.x + threadIdx.x;
    int stride = gridDim.x * blockDim.x;
    for (int j = i; j < NRP; j += stride) {
        int node = j >> 3, p = j & 7;
        g_invC[j] = 1.f / g_colsum[node * p];
        g_invR[j] = 1.f / fmaxf(g_rowsum[node * p], 1e-6f);
    }
}

// ---------------- K6: h[s] = relu(bias1 + sum_{t,p} l1n * W1[o*p]) ----------
__global__ __launch_bounds__(64) void k6_h(
    const int* __restrict__ vcol, const float* __restrict__ W1,
    const float* __restrict__ bias1)
{
    int s = blockIdx.x;
    int tid = threadIdx.x, lane = tid & 31, w = tid >> 5;
    int beg = g_off_s[s], end = g_off_s[s+1];
    __shared__ __align__(16) float sh_l[64][8];
    __shared__ int sh_o32[64];                   // o*32 (float2 row stride)
    const float2* W2p = (const float2*)W1;
    float c0 = 0.f, c1 = 0.f;                    // cols 2*lane, 2*lane+1
    float acc0 = 0.f;                            // p=0 (warp0 only, uniform)

    for (int tile = beg; tile < end; tile += 64) {
        int n = min(64, end - tile);
        if (tid < n) {
            int t = g_perm_s[tile + tid];
            int o = vcol[t];
            sh_o32[tid] = o * 32;
            const float4* lp = (const float4*)(g_l1 + (size_t)t * 8);
            const float4* ip = (const float4*)(g_invC + (size_t)o * 8);
            float4 a = lp[0], b = lp[1], ia = ip[0], ib = ip[1];
            float4* sl = (float4*)&sh_l[tid][0];
            sl[0] = make_float4(a.x*ia.x, a.y*ia.y, a.z*ia.z, a.w*ia.w);
            sl[1] = make_float4(b.x*ib.x, b.y*ib.y, b.z*ib.z, b.w*ib.w);
        }
        __syncthreads();
        int i = 0;
        for (; i + 1 < n; i += 2) {
            int q0 = sh_o32[i], q1 = sh_o32[i+1];
            float4 u0 = *(const float4*)&sh_l[i][0];
            float4 v0 = *(const float4*)&sh_l[i][4];
            float4 u1 = *(const float4*)&sh_l[i+1][0];
            float4 v1 = *(const float4*)&sh_l[i+1][4];
            if (w == 0) {
                float2 A0 = __ldg(&W2p[q0     + lane]);
                float2 B0 = __ldg(&W2p[q0*2   + lane]);
                float2 C0 = __ldg(&W2p[q0*3   + lane]);
                float2 D0 = __ldg(&W2p[q0*7   + lane]);
                float2 A1 = __ldg(&W2p[q1     + lane]);
                float2 B1 = __ldg(&W2p[q1*2   + lane]);
                float2 C1 = __ldg(&W2p[q1*3   + lane]);
                float2 D1 = __ldg(&W2p[q1*7   + lane]);
                acc0 += u0.x + u1.x;
                c0 = fmaf(u0.y, A0.x, c0); c1 = fmaf(u0.y, A0.y, c1);
                c0 = fmaf(u0.z, B0.x, c0); c1 = fmaf(u0.z, B0.y, c1);
                c0 = fmaf(u0.w, C0.x, c0); c1 = fmaf(u0.w, C0.y, c1);
                c0 = fmaf(v0.w, D0.x, c0); c1 = fmaf(v0.w, D0.y, c1);
                c0 = fmaf(u1.y, A1.x, c0); c1 = fmaf(u1.y, A1.y, c1);
                c0 = fmaf(u1.z, B1.x, c0); c1 = fmaf(u1.z, B1.y, c1);
                c0 = fmaf(u1.w, C1.x, c0); c1 = fmaf(u1.w, C1.y, c1);
                c0 = fmaf(v1.w, D1.x, c0); c1 = fmaf(v1.w, D1.y, c1);
            } else {
                float2 A0 = __ldg(&W2p[q0*4   + lane]);
                float2 B0 = __ldg(&W2p[q0*5   + lane]);
                float2 C0 = __ldg(&W2p[q0*6   + lane]);
                float2 A1 = __ldg(&W2p[q1*4   + lane]);
                float2 B1 = __ldg(&W2p[q1*5   + lane]);
                float2 C1 = __ldg(&W2p[q1*6   + lane]);
                c0 = fmaf(v0.x, A0.x, c0); c1 = fmaf(v0.x, A0.y, c1);
                c0 = fmaf(v0.y, B0.x, c0); c1 = fmaf(v0.y, B0.y, c1);
                c0 = fmaf(v0.z, C0.x, c0); c1 = fmaf(v0.z, C0.y, c1);
                c0 = fmaf(v1.x, A1.x, c0); c1 = fmaf(v1.x, A1.y, c1);
                c0 = fmaf(v1.y, B1.x, c0); c1 = fmaf(v1.y, B1.y, c1);
                c0 = fmaf(v1.z, C1.x, c0); c1 = fmaf(v1.z, C1.y, c1);
            }
        }
        if (i < n) {                                 // tail edge
            int q0 = sh_o32[i];
            float4 u0 = *(const float4*)&sh_l[i][0];
            float4 v0 = *(const float4*)&sh_l[i][4];
            if (w == 0) {
                float2 A0 = __ldg(&W2p[q0     + lane]);
                float2 B0 = __ldg(&W2p[q0*2   + lane]);
                float2 C0 = __ldg(&W2p[q0*3   + lane]);
                float2 D0 = __ldg(&W2p[q0*7   + lane]);
                acc0 += u0.x;
                c0 = fmaf(u0.y, A0.x, c0); c1 = fmaf(u0.y, A0.y, c1);
                c0 = fmaf(u0.z, B0.x, c0); c1 = fmaf(u0.z, B0.y, c1);
                c0 = fmaf(u0.w, C0.x, c0); c1 = fmaf(u0.w, C0.y, c1);
                c0 = fmaf(v0.w, D0.x, c0); c1 = fmaf(v0.w, D0.y, c1);
            } else {
                float2 A0 = __ldg(&W2p[q0*4   + lane]);
                float2 B0 = __ldg(&W2p[q0*5   + lane]);
                float2 C0 = __ldg(&W2p[q0*6   + lane]);
                c0 = fmaf(v0.x, A0.x, c0); c1 = fmaf(v0.x, A0.y, c1);
                c0 = fmaf(v0.y, B0.x, c0); c1 = fmaf(v0.y, B0.y, c1);
                c0 = fmaf(v0.z, C0.x, c0); c1 = fmaf(v0.z, C0.y, c1);
            }
        }
        __syncthreads();
    }

    __shared__ float sred[2][64];
    __shared__ float s0;
    sred[w][lane*2] = c0; sred[w][lane*2 + 1] = c1;
    if (tid == 0) s0 = acc0;
    __syncthreads();
    float acc = sred[0][tid] + sred[1][tid] + s0 * __ldg(&W1[tid]);
    g_h[(size_t)s*64 + tid] = fmaxf(acc + bias1[tid], 0.f);
}

// ---------------- K7: fused h2 + einsum -> logits ---------------------------
__global__ __launch_bounds__(64) void k7_logits(
    const int* __restrict__ vcol, const float* __restrict__ W2,
    float* __restrict__ out)
{
    int s = blockIdx.x, tid = threadIdx.x;
    int beg = g_off_s[s], end = g_off_s[s+1];
    if (beg == end) return;
    __shared__ __align__(16) float sh_l[64][8];
    __shared__ int sh_o[64];
    float a[8] = {0.f,0.f,0.f,0.f,0.f,0.f,0.f,0.f};
    const float4* ir = (const float4*)(g_invR + (size_t)s * 8);
    float4 ia = ir[0], ib = ir[1];
    for (int tile = beg; tile < end; tile += 64) {
        int n = min(64, end - tile);
        if (tid < n) {
            int t = g_perm_s[tile + tid];
            int o = vcol[t];
            sh_o[tid] = o;
            const float4* lp = (const float4*)(g_l2 + (size_t)t * 8);
            float4 la = lp[0], lb = lp[1];
            float4* sl = (float4*)&sh_l[tid][0];
            sl[0] = make_float4(la.x*ia.x, la.y*ia.y, la.z*ia.z, la.w*ia.w);
            sl[1] = make_float4(lb.x*ib.x, lb.y*ib.y, lb.z*ib.z, lb.w*ib.w);
        }
        __syncthreads();
        int i = 0;
        for (; i + 1 < n; i += 2) {
            float hv0 = __ldg(&g_h[(size_t)sh_o[i]  *64 + tid]);
            float hv1 = __ldg(&g_h[(size_t)sh_o[i+1]*64 + tid]);
            float4 u0 = *(const float4*)&sh_l[i][0];
            float4 v0 = *(const float4*)&sh_l[i][4];
            float4 u1 = *(const float4*)&sh_l[i+1][0];
            float4 v1 = *(const float4*)&sh_l[i+1][4];
            a[0] = fmaf(u0.x, hv0, a[0]); a[1] = fmaf(u0.y, hv0, a[1]);
            a[2] = fmaf(u0.z, hv0, a[2]); a[3] = fmaf(u0.w, hv0, a[3]);
            a[4] = fmaf(v0.x, hv0, a[4]); a[5] = fmaf(v0.y, hv0, a[5]);
            a[6] = fmaf(v0.z, hv0, a[6]); a[7] = fmaf(v0.w, hv0, a[7]);
            a[0] = fmaf(u1.x, hv1, a[0]); a[1] = fmaf(u1.y, hv1, a[1]);
            a[2] = fmaf(u1.z, hv1, a[2]); a[3] = fmaf(u1.w, hv1, a[3]);
            a[4] = fmaf(v1.x, hv1, a[4]); a[5] = fmaf(v1.y, hv1, a[5]);
            a[6] = fmaf(v1.z, hv1, a[6]); a[7] = fmaf(v1.w, hv1, a[7]);
        }
        if (i < n) {
            float hv0 = __ldg(&g_h[(size_t)sh_o[i]*64 + tid]);
            float4 u0 = *(const float4*)&sh_l[i][0];
            float4 v0 = *(const float4*)&sh_l[i][4];
            a[0] = fmaf(u0.x, hv0, a[0]); a[1] = fmaf(u0.y, hv0, a[1]);
            a[2] = fmaf(u0.z, hv0, a[2]); a[3] = fmaf(u0.w, hv0, a[3]);
            a[4] = fmaf(v0.x, hv0, a[4]); a[5] = fmaf(v0.y, hv0, a[5]);
            a[6] = fmaf(v0.z, hv0, a[6]); a[7] = fmaf(v0.w, hv0, a[7]);
        }
        __syncthreads();
    }
    __shared__ float sh1[8][64];
#pragma unroll
    for (int p = 0; p < 8; p++) sh1[p][tid] = a[p];
    __syncthreads();
    int g = tid >> 4, c = tid & 15;
    float part[8];
#pragma unroll
    for (int p = 0; p < 8; p++) {
        int q = s * p; int r = q / NNODES;
        const float* w2 = W2 + r * (EMB*NC);
        float y = 0.f;
#pragma unroll
        for (int hh = 0; hh < 16; hh++)
            y = fmaf(sh1[p][g*16 + hh], __ldg(&w2[(g*16 + hh)*16 + c]), y);
        part[p] = y;
    }
    __shared__ float sh2[8][64];
#pragma unroll
    for (int p = 0; p < 8; p++) sh2[p][tid] = part[p];
    __syncthreads();
#pragma unroll
    for (int pp = g; pp < 8; pp += 4) {
        float y = sh2[pp][c] + sh2[pp][16+c] + sh2[pp][32+c] + sh2[pp][48+c];
        if (pp == 0) {
            atomicAdd(&g_out0[(s & 63)*16 + c], y);
        } else {
            int q = s * pp; int n_ = q - (q / NNODES) * NNODES;
            atomicAdd(&out[n_*NC + c], y);
        }
    }
}

// ---------------- K8: fold striped p=0 partials into logits row 0 -----------
__global__ void k8_reduce(float* __restrict__ out) {
    int c = threadIdx.x;
    if (c >= 16) return;
    float sum = 0.f;
#pragma unroll
    for (int k = 0; k < 64; k++) sum += g_out0[k*16 + c];
    out[c] += sum;
}

// ---------------- launch ----------------------------------------------------
extern "C" void kernel_launch(void* const* d_in, const int* in_sizes, int n_in,
                              void* d_out, int out_size) {
    const float* rm    = (const float*)d_in[0];
    const int*   hrow  = (const int*)  d_in[1];
    const int*   vcol  = (const int*)  d_in[4];
    const float* Wl1   = (const float*)d_in[5];
    const float* bl1   = (const float*)d_in[6];
    const float* Wl2   = (const float*)d_in[7];
    const float* bl2   = (const float*)d_in[8];
    const float* W1    = (const float*)d_in[9];
    const float* W2    = (const float*)d_in[10];
    const float* bias1 = (const float*)d_in[11];
    const float* bias2 = (const float*)d_in[12];
    float* out = (float*)d_out;

    k0_init    <<<512, 256>>>(out, bias2, hrow);   // 0
    k3_scan    <<<1, 1024>>>();                    // 1
    k4_scatter <<<1024, 256>>>(hrow);              // 2
    k1_l1l2    <<<(NT + 511) / 512, 256>>>(rm, Wl1, bl1, Wl2, bl2, hrow, vcol); // 3 <- profiled
    kinv_tables<<<640, 256>>>();                   // 4
    k6_h       <<<NNODES, 64>>>(vcol, W1, bias1);  // 5
    k7_logits  <<<NNODES, 64>>>(vcol, W2, out);    // 6
    k8_reduce  <<<1, 16>>>(out);                   // 7
}

// round 10
// speedup vs baseline: 1.0112x; 1.0112x over previous
#include <cuda_runtime.h>

#define NT      250000
#define NNODES  20000
#define EMB     64
#define NC      16
#define NRP     (NNODES*8)

// ---------------- scratch ---------------------------------------------------
__device__ __align__(16) float g_l1[NT*8];       // raw l1
__device__ __align__(16) float g_l2[NT*8];       // softmaxed l2
__device__ float g_colsum[NRP];
__device__ float g_rowsum[NRP];
__device__ __align__(16) float g_invC[NRP];      // [o][p] = 1/colsum[o*p]
__device__ __align__(16) float g_invR[NRP];      // [s][p] = 1/max(rowsum[s*p],1e-6)
__device__ __align__(16) float g_h[NNODES*EMB];
__device__ int   g_cnt_s[NNODES];
__device__ int   g_off_s[NNODES+1];
__device__ int   g_cur_s[NNODES];
__device__ int   g_perm_s[NT];
__device__ float g_out0[64*16];                  // striped partials for p=0 logits
__device__ int   g_flag;                         // scan-done flag for k34

// ---------------- K0: zero everything + init logits with bias2 --------------
__global__ void k0_init(float* __restrict__ out, const float* __restrict__ bias2) {
    int i = blockIdx.x * blockDim.x + threadIdx.x;
    int stride = gridDim.x * blockDim.x;
    for (int j = i; j < NRP; j += stride) { g_colsum[j] = 0.f; g_rowsum[j] = 0.f; }
    for (int j = i; j < NNODES; j += stride) g_cnt_s[j] = 0;
    for (int j = i; j < NNODES*NC; j += stride) out[j] = bias2[j & (NC-1)];
    for (int j = i; j < 64*16; j += stride) g_out0[j] = 0.f;
    if (i == 0) g_flag = 0;
}

// ---------------- K1: GEMMs + softmax + sums atomics + s-hist ----------------
// 1 row per thread: regs ~45 -> 5-6 CTAs/SM to hide scattered-atomic latency.
__global__ __launch_bounds__(256) void k1_l1l2(
    const float* __restrict__ rm,
    const float* __restrict__ Wl1, const float* __restrict__ bl1,
    const float* __restrict__ Wl2, const float* __restrict__ bl2,
    const int* __restrict__ hrow, const int* __restrict__ vcol)
{
    __shared__ float4 sW14[128], sW24[128];
    __shared__ float sb1[8], sb2[8];
    int tid = threadIdx.x;
    if (tid < 128) { sW14[tid] = ((const float4*)Wl1)[tid]; sW24[tid] = ((const float4*)Wl2)[tid]; }
    if (tid < 8) { sb1[tid] = bl1[tid]; sb2[tid] = bl2[tid]; }
    __syncthreads();

    int row = blockIdx.x * 256 + tid;
    const float4* rm4 = (const float4*)rm;

    float a1[8], a2[8];
#pragma unroll
    for (int p = 0; p < 8; p++) { a1[p] = sb1[p]; a2[p] = sb2[p]; }

    if (row < NT) {
        for (int k4 = 0; k4 < 16; k4++) {
            float4 x = rm4[(size_t)row * 16 + k4];
#pragma unroll
            for (int j = 0; j < 4; j++) {
                int k = k4 * 4 + j;
                float4 w1lo = sW14[k*2], w1hi = sW14[k*2+1];
                float4 w2lo = sW24[k*2], w2hi = sW24[k*2+1];
                float xv = (j == 0) ? x.x : (j == 1) ? x.y : (j == 2) ? x.z : x.w;
                a1[0] = fmaf(xv, w1lo.x, a1[0]);
                a1[1] = fmaf(xv, w1lo.y, a1[1]);
                a1[2] = fmaf(xv, w1lo.z, a1[2]);
                a1[3] = fmaf(xv, w1lo.w, a1[3]);
                a1[4] = fmaf(xv, w1hi.x, a1[4]);
                a1[5] = fmaf(xv, w1hi.y, a1[5]);
                a1[6] = fmaf(xv, w1hi.z, a1[6]);
                a1[7] = fmaf(xv, w1hi.w, a1[7]);
                a2[0] = fmaf(xv, w2lo.x, a2[0]);
                a2[1] = fmaf(xv, w2lo.y, a2[1]);
                a2[2] = fmaf(xv, w2lo.z, a2[2]);
                a2[3] = fmaf(xv, w2lo.w, a2[3]);
                a2[4] = fmaf(xv, w2hi.x, a2[4]);
                a2[5] = fmaf(xv, w2hi.y, a2[5]);
                a2[6] = fmaf(xv, w2hi.z, a2[6]);
                a2[7] = fmaf(xv, w2hi.w, a2[7]);
            }
        }
    }

    float p0l1 = 0.f, p0l2 = 0.f;
    if (row < NT) {
        float m = a2[0];
#pragma unroll
        for (int p = 1; p < 8; p++) m = fmaxf(m, a2[p]);
        float e[8], ssum = 0.f;
#pragma unroll
        for (int p = 0; p < 8; p++) { e[p] = __expf(a2[p] - m); ssum += e[p]; }
        float inv = 1.f / ssum;
#pragma unroll
        for (int p = 0; p < 8; p++) e[p] *= inv;

        float4* d1 = (float4*)(g_l1 + (size_t)row * 8);
        float4* d2 = (float4*)(g_l2 + (size_t)row * 8);
        d1[0] = make_float4(a1[0], a1[1], a1[2], a1[3]);
        d1[1] = make_float4(a1[4], a1[5], a1[6], a1[7]);
        d2[0] = make_float4(e[0], e[1], e[2], e[3]);
        d2[1] = make_float4(e[4], e[5], e[6], e[7]);

        int o = vcol[row], s = hrow[row];
        p0l1 = a1[0];
        p0l2 = e[0];
#pragma unroll
        for (int p = 1; p < 8; p++) {
            atomicAdd(&g_colsum[o * p], a1[p]);
            atomicAdd(&g_rowsum[s * p], e[p]);
        }
        atomicAdd(&g_cnt_s[s], 1);      // s-histogram (race-free: zeroed in k0)
    }

    int lane = tid & 31, wid = tid >> 5;
#pragma unroll
    for (int d = 16; d > 0; d >>= 1) {
        p0l1 += __shfl_down_sync(0xffffffffu, p0l1, d);
        p0l2 += __shfl_down_sync(0xffffffffu, p0l2, d);
    }
    __shared__ float red1[8], red2[8];
    if (lane == 0) { red1[wid] = p0l1; red2[wid] = p0l2; }
    __syncthreads();
    if (tid == 0) {
        float s1 = 0.f, s2 = 0.f;
#pragma unroll
        for (int w = 0; w < 8; w++) { s1 += red1[w]; s2 += red2[w]; }
        atomicAdd(&g_colsum[0], s1);
        atomicAdd(&g_rowsum[0], s2);
    }
}

// ---------------- K34: scan (block 0) + spin + scatter + inv tables ----------
// 148 blocks x 1024: one per SM, all guaranteed resident -> spin is safe.
__global__ __launch_bounds__(1024) void k34_scan_scatter(const int* __restrict__ hrow) {
    int tid = threadIdx.x, bid = blockIdx.x;

    if (bid == 0) {
        const int CH = 20;                       // 1024*20 = 20480 >= 20000
        int base = tid * CH;
        int loc[CH]; int sum = 0;
#pragma unroll
        for (int j = 0; j < CH; j++) {
            int idx = base + j;
            int v = (idx < NNODES) ? g_cnt_s[idx] : 0;
            loc[j] = v; sum += v;
        }
        int lane = tid & 31, wid = tid >> 5;
        int x = sum;
#pragma unroll
        for (int d = 1; d < 32; d <<= 1) {
            int y = __shfl_up_sync(0xffffffffu, x, d);
            if (lane >= d) x += y;
        }
        __shared__ int wsum[32];
        if (lane == 31) wsum[wid] = x;
        __syncthreads();
        if (wid == 0) {
            int w = wsum[lane];
#pragma unroll
            for (int d = 1; d < 32; d <<= 1) {
                int y = __shfl_up_sync(0xffffffffu, w, d);
                if (lane >= d) w += y;
            }
            wsum[lane] = w;
        }
        __syncthreads();
        int run = x - sum + (wid ? wsum[wid - 1] : 0);
#pragma unroll
        for (int j = 0; j < CH; j++) {
            int idx = base + j;
            if (idx < NNODES) { g_off_s[idx] = run; g_cur_s[idx] = run; run += loc[j]; }
        }
        if (tid == 1023) g_off_s[NNODES] = wsum[31];
        __syncthreads();
        __threadfence();
        if (tid == 0) atomicExch(&g_flag, 1);    // release
    } else {
        if (tid == 0) {
            while (atomicAdd(&g_flag, 0) == 0) __nanosleep(128);   // acquire
        }
        __syncthreads();
    }

    // all blocks: scatter edges into CSR
    int i = bid * 1024 + tid;
    int stride = 148 * 1024;
    for (int t = i; t < NT; t += stride) {
        int p = atomicAdd(&g_cur_s[hrow[t]], 1);
        g_perm_s[p] = t;
    }
    // all blocks: inverse tables (colsum/rowsum complete since k1 finished)
    for (int j = i; j < NRP; j += stride) {
        int node = j >> 3, p = j & 7;
        g_invC[j] = 1.f / g_colsum[node * p];
        g_invR[j] = 1.f / fmaxf(g_rowsum[node * p], 1e-6f);
    }
}

// ---------------- K6: h[s] = relu(bias1 + sum_{t,p} l1n * W1[o*p]) ----------
// (profiled slot: launch index 3) -- identical to R8
__global__ __launch_bounds__(64) void k6_h(
    const int* __restrict__ vcol, const float* __restrict__ W1,
    const float* __restrict__ bias1)
{
    int s = blockIdx.x;
    int tid = threadIdx.x, lane = tid & 31, w = tid >> 5;
    int beg = g_off_s[s], end = g_off_s[s+1];
    __shared__ __align__(16) float sh_l[64][8];
    __shared__ int sh_o32[64];                   // o*32 (float2 row stride)
    const float2* W2p = (const float2*)W1;
    float c0 = 0.f, c1 = 0.f;                    // cols 2*lane, 2*lane+1
    float acc0 = 0.f;                            // p=0 (warp0 only, uniform)

    for (int tile = beg; tile < end; tile += 64) {
        int n = min(64, end - tile);
        if (tid < n) {
            int t = g_perm_s[tile + tid];
            int o = vcol[t];
            sh_o32[tid] = o * 32;
            const float4* lp = (const float4*)(g_l1 + (size_t)t * 8);
            const float4* ip = (const float4*)(g_invC + (size_t)o * 8);
            float4 a = lp[0], b = lp[1], ia = ip[0], ib = ip[1];
            float4* sl = (float4*)&sh_l[tid][0];
            sl[0] = make_float4(a.x*ia.x, a.y*ia.y, a.z*ia.z, a.w*ia.w);
            sl[1] = make_float4(b.x*ib.x, b.y*ib.y, b.z*ib.z, b.w*ib.w);
        }
        __syncthreads();
        int i = 0;
        for (; i + 1 < n; i += 2) {
            int q0 = sh_o32[i], q1 = sh_o32[i+1];
            float4 u0 = *(const float4*)&sh_l[i][0];
            float4 v0 = *(const float4*)&sh_l[i][4];
            float4 u1 = *(const float4*)&sh_l[i+1][0];
            float4 v1 = *(const float4*)&sh_l[i+1][4];
            if (w == 0) {
                float2 A0 = __ldg(&W2p[q0     + lane]);
                float2 B0 = __ldg(&W2p[q0*2   + lane]);
                float2 C0 = __ldg(&W2p[q0*3   + lane]);
                float2 D0 = __ldg(&W2p[q0*7   + lane]);
                float2 A1 = __ldg(&W2p[q1     + lane]);
                float2 B1 = __ldg(&W2p[q1*2   + lane]);
                float2 C1 = __ldg(&W2p[q1*3   + lane]);
                float2 D1 = __ldg(&W2p[q1*7   + lane]);
                acc0 += u0.x + u1.x;
                c0 = fmaf(u0.y, A0.x, c0); c1 = fmaf(u0.y, A0.y, c1);
                c0 = fmaf(u0.z, B0.x, c0); c1 = fmaf(u0.z, B0.y, c1);
                c0 = fmaf(u0.w, C0.x, c0); c1 = fmaf(u0.w, C0.y, c1);
                c0 = fmaf(v0.w, D0.x, c0); c1 = fmaf(v0.w, D0.y, c1);
                c0 = fmaf(u1.y, A1.x, c0); c1 = fmaf(u1.y, A1.y, c1);
                c0 = fmaf(u1.z, B1.x, c0); c1 = fmaf(u1.z, B1.y, c1);
                c0 = fmaf(u1.w, C1.x, c0); c1 = fmaf(u1.w, C1.y, c1);
                c0 = fmaf(v1.w, D1.x, c0); c1 = fmaf(v1.w, D1.y, c1);
            } else {
                float2 A0 = __ldg(&W2p[q0*4   + lane]);
                float2 B0 = __ldg(&W2p[q0*5   + lane]);
                float2 C0 = __ldg(&W2p[q0*6   + lane]);
                float2 A1 = __ldg(&W2p[q1*4   + lane]);
                float2 B1 = __ldg(&W2p[q1*5   + lane]);
                float2 C1 = __ldg(&W2p[q1*6   + lane]);
                c0 = fmaf(v0.x, A0.x, c0); c1 = fmaf(v0.x, A0.y, c1);
                c0 = fmaf(v0.y, B0.x, c0); c1 = fmaf(v0.y, B0.y, c1);
                c0 = fmaf(v0.z, C0.x, c0); c1 = fmaf(v0.z, C0.y, c1);
                c0 = fmaf(v1.x, A1.x, c0); c1 = fmaf(v1.x, A1.y, c1);
                c0 = fmaf(v1.y, B1.x, c0); c1 = fmaf(v1.y, B1.y, c1);
                c0 = fmaf(v1.z, C1.x, c0); c1 = fmaf(v1.z, C1.y, c1);
            }
        }
        if (i < n) {                                 // tail edge
            int q0 = sh_o32[i];
            float4 u0 = *(const float4*)&sh_l[i][0];
            float4 v0 = *(const float4*)&sh_l[i][4];
            if (w == 0) {
                float2 A0 = __ldg(&W2p[q0     + lane]);
                float2 B0 = __ldg(&W2p[q0*2   + lane]);
                float2 C0 = __ldg(&W2p[q0*3   + lane]);
                float2 D0 = __ldg(&W2p[q0*7   + lane]);
                acc0 += u0.x;
                c0 = fmaf(u0.y, A0.x, c0); c1 = fmaf(u0.y, A0.y, c1);
                c0 = fmaf(u0.z, B0.x, c0); c1 = fmaf(u0.z, B0.y, c1);
                c0 = fmaf(u0.w, C0.x, c0); c1 = fmaf(u0.w, C0.y, c1);
                c0 = fmaf(v0.w, D0.x, c0); c1 = fmaf(v0.w, D0.y, c1);
            } else {
                float2 A0 = __ldg(&W2p[q0*4   + lane]);
                float2 B0 = __ldg(&W2p[q0*5   + lane]);
                float2 C0 = __ldg(&W2p[q0*6   + lane]);
                c0 = fmaf(v0.x, A0.x, c0); c1 = fmaf(v0.x, A0.y, c1);
                c0 = fmaf(v0.y, B0.x, c0); c1 = fmaf(v0.y, B0.y, c1);
                c0 = fmaf(v0.z, C0.x, c0); c1 = fmaf(v0.z, C0.y, c1);
            }
        }
        __syncthreads();
    }

    __shared__ float sred[2][64];
    __shared__ float s0;
    sred[w][lane*2] = c0; sred[w][lane*2 + 1] = c1;
    if (tid == 0) s0 = acc0;
    __syncthreads();
    float acc = sred[0][tid] + sred[1][tid] + s0 * __ldg(&W1[tid]);
    g_h[(size_t)s*64 + tid] = fmaxf(acc + bias1[tid], 0.f);
}

// ---------------- K7: fused h2 + einsum -> logits ---------------------------
__global__ __launch_bounds__(64) void k7_logits(
    const int* __restrict__ vcol, const float* __restrict__ W2,
    float* __restrict__ out)
{
    int s = blockIdx.x, tid = threadIdx.x;
    int beg = g_off_s[s], end = g_off_s[s+1];
    if (beg == end) return;
    __shared__ __align__(16) float sh_l[64][8];
    __shared__ int sh_o[64];
    float a[8] = {0.f,0.f,0.f,0.f,0.f,0.f,0.f,0.f};
    const float4* ir = (const float4*)(g_invR + (size_t)s * 8);
    float4 ia = ir[0], ib = ir[1];
    for (int tile = beg; tile < end; tile += 64) {
        int n = min(64, end - tile);
        if (tid < n) {
            int t = g_perm_s[tile + tid];
            int o = vcol[t];
            sh_o[tid] = o;
            const float4* lp = (const float4*)(g_l2 + (size_t)t * 8);
            float4 la = lp[0], lb = lp[1];
            float4* sl = (float4*)&sh_l[tid][0];
            sl[0] = make_float4(la.x*ia.x, la.y*ia.y, la.z*ia.z, la.w*ia.w);
            sl[1] = make_float4(lb.x*ib.x, lb.y*ib.y, lb.z*ib.z, lb.w*ib.w);
        }
        __syncthreads();
        int i = 0;
        for (; i + 1 < n; i += 2) {
            float hv0 = __ldg(&g_h[(size_t)sh_o[i]  *64 + tid]);
            float hv1 = __ldg(&g_h[(size_t)sh_o[i+1]*64 + tid]);
            float4 u0 = *(const float4*)&sh_l[i][0];
            float4 v0 = *(const float4*)&sh_l[i][4];
            float4 u1 = *(const float4*)&sh_l[i+1][0];
            float4 v1 = *(const float4*)&sh_l[i+1][4];
            a[0] = fmaf(u0.x, hv0, a[0]); a[1] = fmaf(u0.y, hv0, a[1]);
            a[2] = fmaf(u0.z, hv0, a[2]); a[3] = fmaf(u0.w, hv0, a[3]);
            a[4] = fmaf(v0.x, hv0, a[4]); a[5] = fmaf(v0.y, hv0, a[5]);
            a[6] = fmaf(v0.z, hv0, a[6]); a[7] = fmaf(v0.w, hv0, a[7]);
            a[0] = fmaf(u1.x, hv1, a[0]); a[1] = fmaf(u1.y, hv1, a[1]);
            a[2] = fmaf(u1.z, hv1, a[2]); a[3] = fmaf(u1.w, hv1, a[3]);
            a[4] = fmaf(v1.x, hv1, a[4]); a[5] = fmaf(v1.y, hv1, a[5]);
            a[6] = fmaf(v1.z, hv1, a[6]); a[7] = fmaf(v1.w, hv1, a[7]);
        }
        if (i < n) {
            float hv0 = __ldg(&g_h[(size_t)sh_o[i]*64 + tid]);
            float4 u0 = *(const float4*)&sh_l[i][0];
            float4 v0 = *(const float4*)&sh_l[i][4];
            a[0] = fmaf(u0.x, hv0, a[0]); a[1] = fmaf(u0.y, hv0, a[1]);
            a[2] = fmaf(u0.z, hv0, a[2]); a[3] = fmaf(u0.w, hv0, a[3]);
            a[4] = fmaf(v0.x, hv0, a[4]); a[5] = fmaf(v0.y, hv0, a[5]);
            a[6] = fmaf(v0.z, hv0, a[6]); a[7] = fmaf(v0.w, hv0, a[7]);
        }
        __syncthreads();
    }
    __shared__ float sh1[8][64];
#pragma unroll
    for (int p = 0; p < 8; p++) sh1[p][tid] = a[p];
    __syncthreads();
    int g = tid >> 4, c = tid & 15;
    float part[8];
#pragma unroll
    for (int p = 0; p < 8; p++) {
        int q = s * p; int r = q / NNODES;
        const float* w2 = W2 + r * (EMB*NC);
        float y = 0.f;
#pragma unroll
        for (int hh = 0; hh < 16; hh++)
            y = fmaf(sh1[p][g*16 + hh], __ldg(&w2[(g*16 + hh)*16 + c]), y);
        part[p] = y;
    }
    __shared__ float sh2[8][64];
#pragma unroll
    for (int p = 0; p < 8; p++) sh2[p][tid] = part[p];
    __syncthreads();
#pragma unroll
    for (int pp = g; pp < 8; pp += 4) {
        float y = sh2[pp][c] + sh2[pp][16+c] + sh2[pp][32+c] + sh2[pp][48+c];
        if (pp == 0) {
            atomicAdd(&g_out0[(s & 63)*16 + c], y);
        } else {
            int q = s * pp; int n_ = q - (q / NNODES) * NNODES;
            atomicAdd(&out[n_*NC + c], y);
        }
    }
}

// ---------------- K8: fold striped p=0 partials into logits row 0 -----------
__global__ void k8_reduce(float* __restrict__ out) {
    int c = threadIdx.x;
    if (c >= 16) return;
    float sum = 0.f;
#pragma unroll
    for (int k = 0; k < 64; k++) sum += g_out0[k*16 + c];
    out[c] += sum;
}

// ---------------- launch ----------------------------------------------------
extern "C" void kernel_launch(void* const* d_in, const int* in_sizes, int n_in,
                              void* d_out, int out_size) {
    const float* rm    = (const float*)d_in[0];
    const int*   hrow  = (const int*)  d_in[1];
    const int*   vcol  = (const int*)  d_in[4];
    const float* Wl1   = (const float*)d_in[5];
    const float* bl1   = (const float*)d_in[6];
    const float* Wl2   = (const float*)d_in[7];
    const float* bl2   = (const float*)d_in[8];
    const float* W1    = (const float*)d_in[9];
    const float* W2    = (const float*)d_in[10];
    const float* bias1 = (const float*)d_in[11];
    const float* bias2 = (const float*)d_in[12];
    float* out = (float*)d_out;

    k0_init         <<<512, 256>>>(out, bias2);                                  // 0
    k1_l1l2         <<<(NT + 255) / 256, 256>>>(rm, Wl1, bl1, Wl2, bl2, hrow, vcol); // 1
    k34_scan_scatter<<<148, 1024>>>(hrow);                                       // 2
    k6_h            <<<NNODES, 64>>>(vcol, W1, bias1);                           // 3 <- profiled
    k7_logits       <<<NNODES, 64>>>(vcol, W2, out);                             // 4
    k8_reduce       <<<1, 16>>>(out);                                            // 5
}

// round 11
// speedup vs baseline: 1.0203x; 1.0090x over previous
#include <cuda_runtime.h>

#define NT      250000
#define NNODES  20000
#define EMB     64
#define NC      16
#define NRP     (NNODES*8)

// ---------------- scratch (statically zero-initialized at module load) ------
// Self-cleaning invariant: every call leaves colsum/rowsum/cnt_s/g_out0/g_flag
// zeroed again (k6/k8 epilogues), so no separate zeroing kernel is needed.
__device__ __align__(16) float g_l1[NT*8];       // raw l1
__device__ __align__(16) float g_l2[NT*8];       // softmaxed l2
__device__ float g_colsum[NRP];
__device__ float g_rowsum[NRP];
__device__ __align__(16) float g_invC[NRP];      // [o][p] = 1/colsum[o*p]
__device__ __align__(16) float g_invR[NRP];      // [s][p] = 1/max(rowsum[s*p],1e-6)
__device__ __align__(16) float g_h[NNODES*EMB];
__device__ int   g_cnt_s[NNODES];
__device__ int   g_off_s[NNODES+1];
__device__ int   g_cur_s[NNODES];
__device__ int   g_perm_s[NT];
__device__ float g_out0[64*16];                  // striped partials for p=0 logits
__device__ int   g_flag;                         // scan-done flag for k34

// ---------------- K1: GEMMs + softmax + sums atomics + s-hist ----------------
__global__ __launch_bounds__(256) void k1_l1l2(
    const float* __restrict__ rm,
    const float* __restrict__ Wl1, const float* __restrict__ bl1,
    const float* __restrict__ Wl2, const float* __restrict__ bl2,
    const int* __restrict__ hrow, const int* __restrict__ vcol)
{
    __shared__ float4 sW14[128], sW24[128];
    __shared__ float sb1[8], sb2[8];
    int tid = threadIdx.x;
    if (tid < 128) { sW14[tid] = ((const float4*)Wl1)[tid]; sW24[tid] = ((const float4*)Wl2)[tid]; }
    if (tid < 8) { sb1[tid] = bl1[tid]; sb2[tid] = bl2[tid]; }
    __syncthreads();

    int row = blockIdx.x * 256 + tid;
    const float4* rm4 = (const float4*)rm;

    float a1[8], a2[8];
#pragma unroll
    for (int p = 0; p < 8; p++) { a1[p] = sb1[p]; a2[p] = sb2[p]; }

    if (row < NT) {
        for (int k4 = 0; k4 < 16; k4++) {
            float4 x = rm4[(size_t)row * 16 + k4];
#pragma unroll
            for (int j = 0; j < 4; j++) {
                int k = k4 * 4 + j;
                float4 w1lo = sW14[k*2], w1hi = sW14[k*2+1];
                float4 w2lo = sW24[k*2], w2hi = sW24[k*2+1];
                float xv = (j == 0) ? x.x : (j == 1) ? x.y : (j == 2) ? x.z : x.w;
                a1[0] = fmaf(xv, w1lo.x, a1[0]);
                a1[1] = fmaf(xv, w1lo.y, a1[1]);
                a1[2] = fmaf(xv, w1lo.z, a1[2]);
                a1[3] = fmaf(xv, w1lo.w, a1[3]);
                a1[4] = fmaf(xv, w1hi.x, a1[4]);
                a1[5] = fmaf(xv, w1hi.y, a1[5]);
                a1[6] = fmaf(xv, w1hi.z, a1[6]);
                a1[7] = fmaf(xv, w1hi.w, a1[7]);
                a2[0] = fmaf(xv, w2lo.x, a2[0]);
                a2[1] = fmaf(xv, w2lo.y, a2[1]);
                a2[2] = fmaf(xv, w2lo.z, a2[2]);
                a2[3] = fmaf(xv, w2lo.w, a2[3]);
                a2[4] = fmaf(xv, w2hi.x, a2[4]);
                a2[5] = fmaf(xv, w2hi.y, a2[5]);
                a2[6] = fmaf(xv, w2hi.z, a2[6]);
                a2[7] = fmaf(xv, w2hi.w, a2[7]);
            }
        }
    }

    float p0l1 = 0.f, p0l2 = 0.f;
    if (row < NT) {
        float m = a2[0];
#pragma unroll
        for (int p = 1; p < 8; p++) m = fmaxf(m, a2[p]);
        float e[8], ssum = 0.f;
#pragma unroll
        for (int p = 0; p < 8; p++) { e[p] = __expf(a2[p] - m); ssum += e[p]; }
        float inv = 1.f / ssum;
#pragma unroll
        for (int p = 0; p < 8; p++) e[p] *= inv;

        float4* d1 = (float4*)(g_l1 + (size_t)row * 8);
        float4* d2 = (float4*)(g_l2 + (size_t)row * 8);
        d1[0] = make_float4(a1[0], a1[1], a1[2], a1[3]);
        d1[1] = make_float4(a1[4], a1[5], a1[6], a1[7]);
        d2[0] = make_float4(e[0], e[1], e[2], e[3]);
        d2[1] = make_float4(e[4], e[5], e[6], e[7]);

        int o = vcol[row], s = hrow[row];
        p0l1 = a1[0];
        p0l2 = e[0];
#pragma unroll
        for (int p = 1; p < 8; p++) {
            atomicAdd(&g_colsum[o * p], a1[p]);
            atomicAdd(&g_rowsum[s * p], e[p]);
        }
        atomicAdd(&g_cnt_s[s], 1);      // zeroed by previous call's k6 (or static init)
    }

    int lane = tid & 31, wid = tid >> 5;
#pragma unroll
    for (int d = 16; d > 0; d >>= 1) {
        p0l1 += __shfl_down_sync(0xffffffffu, p0l1, d);
        p0l2 += __shfl_down_sync(0xffffffffu, p0l2, d);
    }
    __shared__ float red1[8], red2[8];
    if (lane == 0) { red1[wid] = p0l1; red2[wid] = p0l2; }
    __syncthreads();
    if (tid == 0) {
        float s1 = 0.f, s2 = 0.f;
#pragma unroll
        for (int w = 0; w < 8; w++) { s1 += red1[w]; s2 += red2[w]; }
        atomicAdd(&g_colsum[0], s1);
        atomicAdd(&g_rowsum[0], s2);
    }
}

// ---------------- K34: scan + spin + scatter + inv tables + out init --------
// 148 blocks x 1024: one per SM, all guaranteed resident -> spin is safe.
__global__ __launch_bounds__(1024) void k34_scan_scatter(
    const int* __restrict__ hrow,
    float* __restrict__ out, const float* __restrict__ bias2)
{
    int tid = threadIdx.x, bid = blockIdx.x;

    if (bid == 0) {
        const int CH = 20;                       // 1024*20 = 20480 >= 20000
        int base = tid * CH;
        int loc[CH]; int sum = 0;
#pragma unroll
        for (int j = 0; j < CH; j++) {
            int idx = base + j;
            int v = (idx < NNODES) ? g_cnt_s[idx] : 0;
            loc[j] = v; sum += v;
        }
        int lane = tid & 31, wid = tid >> 5;
        int x = sum;
#pragma unroll
        for (int d = 1; d < 32; d <<= 1) {
            int y = __shfl_up_sync(0xffffffffu, x, d);
            if (lane >= d) x += y;
        }
        __shared__ int wsum[32];
        if (lane == 31) wsum[wid] = x;
        __syncthreads();
        if (wid == 0) {
            int w = wsum[lane];
#pragma unroll
            for (int d = 1; d < 32; d <<= 1) {
                int y = __shfl_up_sync(0xffffffffu, w, d);
                if (lane >= d) w += y;
            }
            wsum[lane] = w;
        }
        __syncthreads();
        int run = x - sum + (wid ? wsum[wid - 1] : 0);
#pragma unroll
        for (int j = 0; j < CH; j++) {
            int idx = base + j;
            if (idx < NNODES) { g_off_s[idx] = run; g_cur_s[idx] = run; run += loc[j]; }
        }
        if (tid == 1023) g_off_s[NNODES] = wsum[31];
        __syncthreads();
        __threadfence();
        if (tid == 0) atomicExch(&g_flag, 1);    // release
    } else {
        if (tid == 0) {
            while (atomicAdd(&g_flag, 0) == 0) __nanosleep(128);   // acquire
        }
        __syncthreads();
    }

    int i = bid * 1024 + tid;
    int stride = 148 * 1024;
    // scatter edges into CSR
    for (int t = i; t < NT; t += stride) {
        int p = atomicAdd(&g_cur_s[hrow[t]], 1);
        g_perm_s[p] = t;
    }
    // inverse tables (colsum/rowsum complete since k1 finished)
    for (int j = i; j < NRP; j += stride) {
        int node = j >> 3, p = j & 7;
        g_invC[j] = 1.f / g_colsum[node * p];
        g_invR[j] = 1.f / fmaxf(g_rowsum[node * p], 1e-6f);
    }
    // init logits with bias2 (d_out is poisoned each timing run)
    for (int j = i; j < NNODES*NC; j += stride) out[j] = bias2[j & (NC-1)];
}

// ---------------- K6: h[s] = relu(bias1 + sum) + cleanup for next call ------
__global__ __launch_bounds__(64) void k6_h(
    const int* __restrict__ vcol, const float* __restrict__ W1,
    const float* __restrict__ bias1)
{
    int s = blockIdx.x;
    int tid = threadIdx.x, lane = tid & 31, w = tid >> 5;

    // --- self-cleaning: zero accumulators for the NEXT call (last readers ran in k34)
    {
        int gi = s * 64 + tid;                   // 1.28M threads cover NRP=160K
        if (gi < NRP) { g_colsum[gi] = 0.f; g_rowsum[gi] = 0.f; }
        if (gi < NNODES) g_cnt_s[gi] = 0;
        if (gi == 0) g_flag = 0;
    }

    int beg = g_off_s[s], end = g_off_s[s+1];
    __shared__ __align__(16) float sh_l[64][8];
    __shared__ int sh_o32[64];                   // o*32 (float2 row stride)
    const float2* W2p = (const float2*)W1;
    float c0 = 0.f, c1 = 0.f;                    // cols 2*lane, 2*lane+1
    float acc0 = 0.f;                            // p=0 (warp0 only, uniform)

    for (int tile = beg; tile < end; tile += 64) {
        int n = min(64, end - tile);
        if (tid < n) {
            int t = g_perm_s[tile + tid];
            int o = vcol[t];
            sh_o32[tid] = o * 32;
            const float4* lp = (const float4*)(g_l1 + (size_t)t * 8);
            const float4* ip = (const float4*)(g_invC + (size_t)o * 8);
            float4 a = lp[0], b = lp[1], ia = ip[0], ib = ip[1];
            float4* sl = (float4*)&sh_l[tid][0];
            sl[0] = make_float4(a.x*ia.x, a.y*ia.y, a.z*ia.z, a.w*ia.w);
            sl[1] = make_float4(b.x*ib.x, b.y*ib.y, b.z*ib.z, b.w*ib.w);
        }
        __syncthreads();
        int i = 0;
        for (; i + 1 < n; i += 2) {
            int q0 = sh_o32[i], q1 = sh_o32[i+1];
            float4 u0 = *(const float4*)&sh_l[i][0];
            float4 v0 = *(const float4*)&sh_l[i][4];
            float4 u1 = *(const float4*)&sh_l[i+1][0];
            float4 v1 = *(const float4*)&sh_l[i+1][4];
            if (w == 0) {
                float2 A0 = __ldg(&W2p[q0     + lane]);
                float2 B0 = __ldg(&W2p[q0*2   + lane]);
                float2 C0 = __ldg(&W2p[q0*3   + lane]);
                float2 D0 = __ldg(&W2p[q0*7   + lane]);
                float2 A1 = __ldg(&W2p[q1     + lane]);
                float2 B1 = __ldg(&W2p[q1*2   + lane]);
                float2 C1 = __ldg(&W2p[q1*3   + lane]);
                float2 D1 = __ldg(&W2p[q1*7   + lane]);
                acc0 += u0.x + u1.x;
                c0 = fmaf(u0.y, A0.x, c0); c1 = fmaf(u0.y, A0.y, c1);
                c0 = fmaf(u0.z, B0.x, c0); c1 = fmaf(u0.z, B0.y, c1);
                c0 = fmaf(u0.w, C0.x, c0); c1 = fmaf(u0.w, C0.y, c1);
                c0 = fmaf(v0.w, D0.x, c0); c1 = fmaf(v0.w, D0.y, c1);
                c0 = fmaf(u1.y, A1.x, c0); c1 = fmaf(u1.y, A1.y, c1);
                c0 = fmaf(u1.z, B1.x, c0); c1 = fmaf(u1.z, B1.y, c1);
                c0 = fmaf(u1.w, C1.x, c0); c1 = fmaf(u1.w, C1.y, c1);
                c0 = fmaf(v1.w, D1.x, c0); c1 = fmaf(v1.w, D1.y, c1);
            } else {
                float2 A0 = __ldg(&W2p[q0*4   + lane]);
                float2 B0 = __ldg(&W2p[q0*5   + lane]);
                float2 C0 = __ldg(&W2p[q0*6   + lane]);
                float2 A1 = __ldg(&W2p[q1*4   + lane]);
                float2 B1 = __ldg(&W2p[q1*5   + lane]);
                float2 C1 = __ldg(&W2p[q1*6   + lane]);
                c0 = fmaf(v0.x, A0.x, c0); c1 = fmaf(v0.x, A0.y, c1);
                c0 = fmaf(v0.y, B0.x, c0); c1 = fmaf(v0.y, B0.y, c1);
                c0 = fmaf(v0.z, C0.x, c0); c1 = fmaf(v0.z, C0.y, c1);
                c0 = fmaf(v1.x, A1.x, c0); c1 = fmaf(v1.x, A1.y, c1);
                c0 = fmaf(v1.y, B1.x, c0); c1 = fmaf(v1.y, B1.y, c1);
                c0 = fmaf(v1.z, C1.x, c0); c1 = fmaf(v1.z, C1.y, c1);
            }
        }
        if (i < n) {                                 // tail edge
            int q0 = sh_o32[i];
            float4 u0 = *(const float4*)&sh_l[i][0];
            float4 v0 = *(const float4*)&sh_l[i][4];
            if (w == 0) {
                float2 A0 = __ldg(&W2p[q0     + lane]);
                float2 B0 = __ldg(&W2p[q0*2   + lane]);
                float2 C0 = __ldg(&W2p[q0*3   + lane]);
                float2 D0 = __ldg(&W2p[q0*7   + lane]);
                acc0 += u0.x;
                c0 = fmaf(u0.y, A0.x, c0); c1 = fmaf(u0.y, A0.y, c1);
                c0 = fmaf(u0.z, B0.x, c0); c1 = fmaf(u0.z, B0.y, c1);
                c0 = fmaf(u0.w, C0.x, c0); c1 = fmaf(u0.w, C0.y, c1);
                c0 = fmaf(v0.w, D0.x, c0); c1 = fmaf(v0.w, D0.y, c1);
            } else {
                float2 A0 = __ldg(&W2p[q0*4   + lane]);
                float2 B0 = __ldg(&W2p[q0*5   + lane]);
                float2 C0 = __ldg(&W2p[q0*6   + lane]);
                c0 = fmaf(v0.x, A0.x, c0); c1 = fmaf(v0.x, A0.y, c1);
                c0 = fmaf(v0.y, B0.x, c0); c1 = fmaf(v0.y, B0.y, c1);
                c0 = fmaf(v0.z, C0.x, c0); c1 = fmaf(v0.z, C0.y, c1);
            }
        }
        __syncthreads();
    }

    __shared__ float sred[2][64];
    __shared__ float s0;
    sred[w][lane*2] = c0; sred[w][lane*2 + 1] = c1;
    if (tid == 0) s0 = acc0;
    __syncthreads();
    float acc = sred[0][tid] + sred[1][tid] + s0 * __ldg(&W1[tid]);
    g_h[(size_t)s*64 + tid] = fmaxf(acc + bias1[tid], 0.f);
}

// ---------------- K7: fused h2 + einsum -> logits (profiled slot, idx 3) ----
__global__ __launch_bounds__(64) void k7_logits(
    const int* __restrict__ vcol, const float* __restrict__ W2,
    float* __restrict__ out)
{
    int s = blockIdx.x, tid = threadIdx.x;
    int beg = g_off_s[s], end = g_off_s[s+1];
    if (beg == end) return;
    __shared__ __align__(16) float sh_l[64][8];
    __shared__ int sh_o[64];
    float a[8] = {0.f,0.f,0.f,0.f,0.f,0.f,0.f,0.f};
    const float4* ir = (const float4*)(g_invR + (size_t)s * 8);
    float4 ia = ir[0], ib = ir[1];
    for (int tile = beg; tile < end; tile += 64) {
        int n = min(64, end - tile);
        if (tid < n) {
            int t = g_perm_s[tile + tid];
            int o = vcol[t];
            sh_o[tid] = o;
            const float4* lp = (const float4*)(g_l2 + (size_t)t * 8);
            float4 la = lp[0], lb = lp[1];
            float4* sl = (float4*)&sh_l[tid][0];
            sl[0] = make_float4(la.x*ia.x, la.y*ia.y, la.z*ia.z, la.w*ia.w);
            sl[1] = make_float4(lb.x*ib.x, lb.y*ib.y, lb.z*ib.z, lb.w*ib.w);
        }
        __syncthreads();
        int i = 0;
        for (; i + 1 < n; i += 2) {
            float hv0 = __ldg(&g_h[(size_t)sh_o[i]  *64 + tid]);
            float hv1 = __ldg(&g_h[(size_t)sh_o[i+1]*64 + tid]);
            float4 u0 = *(const float4*)&sh_l[i][0];
            float4 v0 = *(const float4*)&sh_l[i][4];
            float4 u1 = *(const float4*)&sh_l[i+1][0];
            float4 v1 = *(const float4*)&sh_l[i+1][4];
            a[0] = fmaf(u0.x, hv0, a[0]); a[1] = fmaf(u0.y, hv0, a[1]);
            a[2] = fmaf(u0.z, hv0, a[2]); a[3] = fmaf(u0.w, hv0, a[3]);
            a[4] = fmaf(v0.x, hv0, a[4]); a[5] = fmaf(v0.y, hv0, a[5]);
            a[6] = fmaf(v0.z, hv0, a[6]); a[7] = fmaf(v0.w, hv0, a[7]);
            a[0] = fmaf(u1.x, hv1, a[0]); a[1] = fmaf(u1.y, hv1, a[1]);
            a[2] = fmaf(u1.z, hv1, a[2]); a[3] = fmaf(u1.w, hv1, a[3]);
            a[4] = fmaf(v1.x, hv1, a[4]); a[5] = fmaf(v1.y, hv1, a[5]);
            a[6] = fmaf(v1.z, hv1, a[6]); a[7] = fmaf(v1.w, hv1, a[7]);
        }
        if (i < n) {
            float hv0 = __ldg(&g_h[(size_t)sh_o[i]*64 + tid]);
            float4 u0 = *(const float4*)&sh_l[i][0];
            float4 v0 = *(const float4*)&sh_l[i][4];
            a[0] = fmaf(u0.x, hv0, a[0]); a[1] = fmaf(u0.y, hv0, a[1]);
            a[2] = fmaf(u0.z, hv0, a[2]); a[3] = fmaf(u0.w, hv0, a[3]);
            a[4] = fmaf(v0.x, hv0, a[4]); a[5] = fmaf(v0.y, hv0, a[5]);
            a[6] = fmaf(v0.z, hv0, a[6]); a[7] = fmaf(v0.w, hv0, a[7]);
        }
        __syncthreads();
    }
    __shared__ float sh1[8][64];
#pragma unroll
    for (int p = 0; p < 8; p++) sh1[p][tid] = a[p];
    __syncthreads();
    int g = tid >> 4, c = tid & 15;
    float part[8];
#pragma unroll
    for (int p = 0; p < 8; p++) {
        int q = s * p; int r = q / NNODES;
        const float* w2 = W2 + r * (EMB*NC);
        float y = 0.f;
#pragma unroll
        for (int hh = 0; hh < 16; hh++)
            y = fmaf(sh1[p][g*16 + hh], __ldg(&w2[(g*16 + hh)*16 + c]), y);
        part[p] = y;
    }
    __shared__ float sh2[8][64];
#pragma unroll
    for (int p = 0; p < 8; p++) sh2[p][tid] = part[p];
    __syncthreads();
#pragma unroll
    for (int pp = g; pp < 8; pp += 4) {
        float y = sh2[pp][c] + sh2[pp][16+c] + sh2[pp][32+c] + sh2[pp][48+c];
        if (pp == 0) {
            atomicAdd(&g_out0[(s & 63)*16 + c], y);
        } else {
            int q = s * pp; int n_ = q - (q / NNODES) * NNODES;
            atomicAdd(&out[n_*NC + c], y);
        }
    }
}

// ---------------- K8: fold striped p=0 partials + zero g_out0 for next call -
__global__ void k8_reduce(float* __restrict__ out) {
    int c = threadIdx.x;
    if (c >= 16) return;
    float sum = 0.f;
#pragma unroll
    for (int k = 0; k < 64; k++) sum += g_out0[k*16 + c];
    out[c] += sum;
#pragma unroll
    for (int k = 0; k < 64; k++) g_out0[k*16 + c] = 0.f;   // self-clean
}

// ---------------- launch ----------------------------------------------------
extern "C" void kernel_launch(void* const* d_in, const int* in_sizes, int n_in,
                              void* d_out, int out_size) {
    const float* rm    = (const float*)d_in[0];
    const int*   hrow  = (const int*)  d_in[1];
    const int*   vcol  = (const int*)  d_in[4];
    const float* Wl1   = (const float*)d_in[5];
    const float* bl1   = (const float*)d_in[6];
    const float* Wl2   = (const float*)d_in[7];
    const float* bl2   = (const float*)d_in[8];
    const float* W1    = (const float*)d_in[9];
    const float* W2    = (const float*)d_in[10];
    const float* bias1 = (const float*)d_in[11];
    const float* bias2 = (const float*)d_in[12];
    float* out = (float*)d_out;

    k1_l1l2         <<<(NT + 255) / 256, 256>>>(rm, Wl1, bl1, Wl2, bl2, hrow, vcol); // 0
    k34_scan_scatter<<<148, 1024>>>(hrow, out, bias2);                               // 1
    k6_h            <<<NNODES, 64>>>(vcol, W1, bias1);                               // 2
    k7_logits       <<<NNODES, 64>>>(vcol, W2, out);                                 // 3 <- profiled
    k8_reduce       <<<1, 16>>>(out);                                                // 4
}

// round 13
// speedup vs baseline: 1.1020x; 1.0801x over previous
#include <cuda_runtime.h>

#define NT      250000
#define NNODES  20000
#define EMB     64
#define NC      16
#define NRP     (NNODES*8)

// ---------------- scratch (statically zero-initialized at module load) ------
__device__ __align__(16) float g_l1[NT*8];       // raw l1
__device__ __align__(16) float g_l2[NT*8];       // softmaxed l2
__device__ float g_colsum[NRP];
__device__ float g_rowsum[NRP];
__device__ __align__(16) float g_invC[NRP];      // [o][p] = 1/colsum[o*p]
__device__ __align__(16) float g_invR[NRP];      // [s][p] = 1/max(rowsum[s*p],1e-6)
__device__ __align__(16) float g_h[NNODES*EMB];
__device__ __align__(16) float g_h2[NNODES*128]; // H2[o][r*16+c] = h[o] @ W2[r]
__device__ int   g_cnt_s[NNODES];
__device__ int   g_off_s[NNODES+1];
__device__ int   g_cur_s[NNODES];
__device__ int   g_perm_s[NT];
__device__ float g_out0[64*16];                  // striped partials for p=0 logits
__device__ int   g_flag;                         // scan-done flag for k34

// ---------------- K1: GEMMs + softmax + sums atomics + s-hist ----------------
__global__ __launch_bounds__(256) void k1_l1l2(
    const float* __restrict__ rm,
    const float* __restrict__ Wl1, const float* __restrict__ bl1,
    const float* __restrict__ Wl2, const float* __restrict__ bl2,
    const int* __restrict__ hrow, const int* __restrict__ vcol)
{
    __shared__ float4 sW14[128], sW24[128];
    __shared__ float sb1[8], sb2[8];
    int tid = threadIdx.x;
    if (tid < 128) { sW14[tid] = ((const float4*)Wl1)[tid]; sW24[tid] = ((const float4*)Wl2)[tid]; }
    if (tid < 8) { sb1[tid] = bl1[tid]; sb2[tid] = bl2[tid]; }
    __syncthreads();

    int row = blockIdx.x * 256 + tid;
    const float4* rm4 = (const float4*)rm;

    float a1[8], a2[8];
#pragma unroll
    for (int p = 0; p < 8; p++) { a1[p] = sb1[p]; a2[p] = sb2[p]; }

    if (row < NT) {
        for (int k4 = 0; k4 < 16; k4++) {
            float4 x = rm4[(size_t)row * 16 + k4];
#pragma unroll
            for (int j = 0; j < 4; j++) {
                int k = k4 * 4 + j;
                float4 w1lo = sW14[k*2], w1hi = sW14[k*2+1];
                float4 w2lo = sW24[k*2], w2hi = sW24[k*2+1];
                float xv = (j == 0) ? x.x : (j == 1) ? x.y : (j == 2) ? x.z : x.w;
                a1[0] = fmaf(xv, w1lo.x, a1[0]);
                a1[1] = fmaf(xv, w1lo.y, a1[1]);
                a1[2] = fmaf(xv, w1lo.z, a1[2]);
                a1[3] = fmaf(xv, w1lo.w, a1[3]);
                a1[4] = fmaf(xv, w1hi.x, a1[4]);
                a1[5] = fmaf(xv, w1hi.y, a1[5]);
                a1[6] = fmaf(xv, w1hi.z, a1[6]);
                a1[7] = fmaf(xv, w1hi.w, a1[7]);
                a2[0] = fmaf(xv, w2lo.x, a2[0]);
                a2[1] = fmaf(xv, w2lo.y, a2[1]);
                a2[2] = fmaf(xv, w2lo.z, a2[2]);
                a2[3] = fmaf(xv, w2lo.w, a2[3]);
                a2[4] = fmaf(xv, w2hi.x, a2[4]);
                a2[5] = fmaf(xv, w2hi.y, a2[5]);
                a2[6] = fmaf(xv, w2hi.z, a2[6]);
                a2[7] = fmaf(xv, w2hi.w, a2[7]);
            }
        }
    }

    float p0l1 = 0.f, p0l2 = 0.f;
    if (row < NT) {
        float m = a2[0];
#pragma unroll
        for (int p = 1; p < 8; p++) m = fmaxf(m, a2[p]);
        float e[8], ssum = 0.f;
#pragma unroll
        for (int p = 0; p < 8; p++) { e[p] = __expf(a2[p] - m); ssum += e[p]; }
        float inv = 1.f / ssum;
#pragma unroll
        for (int p = 0; p < 8; p++) e[p] *= inv;

        float4* d1 = (float4*)(g_l1 + (size_t)row * 8);
        float4* d2 = (float4*)(g_l2 + (size_t)row * 8);
        d1[0] = make_float4(a1[0], a1[1], a1[2], a1[3]);
        d1[1] = make_float4(a1[4], a1[5], a1[6], a1[7]);
        d2[0] = make_float4(e[0], e[1], e[2], e[3]);
        d2[1] = make_float4(e[4], e[5], e[6], e[7]);

        int o = vcol[row], s = hrow[row];
        p0l1 = a1[0];
        p0l2 = e[0];
#pragma unroll
        for (int p = 1; p < 8; p++) {
            atomicAdd(&g_colsum[o * p], a1[p]);
            atomicAdd(&g_rowsum[s * p], e[p]);
        }
        atomicAdd(&g_cnt_s[s], 1);      // zeroed by previous call's k6 (or static init)
    }

    int lane = tid & 31, wid = tid >> 5;
#pragma unroll
    for (int d = 16; d > 0; d >>= 1) {
        p0l1 += __shfl_down_sync(0xffffffffu, p0l1, d);
        p0l2 += __shfl_down_sync(0xffffffffu, p0l2, d);
    }
    __shared__ float red1[8], red2[8];
    if (lane == 0) { red1[wid] = p0l1; red2[wid] = p0l2; }
    __syncthreads();
    if (tid == 0) {
        float s1 = 0.f, s2 = 0.f;
#pragma unroll
        for (int w = 0; w < 8; w++) { s1 += red1[w]; s2 += red2[w]; }
        atomicAdd(&g_colsum[0], s1);
        atomicAdd(&g_rowsum[0], s2);
    }
}

// ---------------- K34: scan + spin + scatter + inv tables + out init --------
__global__ __launch_bounds__(1024) void k34_scan_scatter(
    const int* __restrict__ hrow,
    float* __restrict__ out, const float* __restrict__ bias2)
{
    int tid = threadIdx.x, bid = blockIdx.x;

    if (bid == 0) {
        const int CH = 20;
        int base = tid * CH;
        int loc[CH]; int sum = 0;
#pragma unroll
        for (int j = 0; j < CH; j++) {
            int idx = base + j;
            int v = (idx < NNODES) ? g_cnt_s[idx] : 0;
            loc[j] = v; sum += v;
        }
        int lane = tid & 31, wid = tid >> 5;
        int x = sum;
#pragma unroll
        for (int d = 1; d < 32; d <<= 1) {
            int y = __shfl_up_sync(0xffffffffu, x, d);
            if (lane >= d) x += y;
        }
        __shared__ int wsum[32];
        if (lane == 31) wsum[wid] = x;
        __syncthreads();
        if (wid == 0) {
            int w = wsum[lane];
#pragma unroll
            for (int d = 1; d < 32; d <<= 1) {
                int y = __shfl_up_sync(0xffffffffu, w, d);
                if (lane >= d) w += y;
            }
            wsum[lane] = w;
        }
        __syncthreads();
        int run = x - sum + (wid ? wsum[wid - 1] : 0);
#pragma unroll
        for (int j = 0; j < CH; j++) {
            int idx = base + j;
            if (idx < NNODES) { g_off_s[idx] = run; g_cur_s[idx] = run; run += loc[j]; }
        }
        if (tid == 1023) g_off_s[NNODES] = wsum[31];
        __syncthreads();
        __threadfence();
        if (tid == 0) atomicExch(&g_flag, 1);    // release
    } else {
        if (tid == 0) {
            while (atomicAdd(&g_flag, 0) == 0) __nanosleep(128);   // acquire
        }
        __syncthreads();
    }

    int i = bid * 1024 + tid;
    int stride = 148 * 1024;
    for (int t = i; t < NT; t += stride) {
        int p = atomicAdd(&g_cur_s[hrow[t]], 1);
        g_perm_s[p] = t;
    }
    for (int j = i; j < NRP; j += stride) {
        int node = j >> 3, p = j & 7;
        g_invC[j] = 1.f / g_colsum[node * p];
        g_invR[j] = 1.f / fmaxf(g_rowsum[node * p], 1e-6f);
    }
    for (int j = i; j < NNODES*NC; j += stride) out[j] = bias2[j & (NC-1)];
}

// ---------------- K6: h[s] = relu(bias1 + sum) + cleanup for next call ------
__global__ __launch_bounds__(64) void k6_h(
    const int* __restrict__ vcol, const float* __restrict__ W1,
    const float* __restrict__ bias1)
{
    int s = blockIdx.x;
    int tid = threadIdx.x, lane = tid & 31, w = tid >> 5;

    {   // self-cleaning for next call
        int gi = s * 64 + tid;
        if (gi < NRP) { g_colsum[gi] = 0.f; g_rowsum[gi] = 0.f; }
        if (gi < NNODES) g_cnt_s[gi] = 0;
        if (gi == 0) g_flag = 0;
    }

    int beg = g_off_s[s], end = g_off_s[s+1];
    __shared__ __align__(16) float sh_l[64][8];
    __shared__ int sh_o32[64];
    const float2* W2p = (const float2*)W1;
    float c0 = 0.f, c1 = 0.f;
    float acc0 = 0.f;

    for (int tile = beg; tile < end; tile += 64) {
        int n = min(64, end - tile);
        if (tid < n) {
            int t = g_perm_s[tile + tid];
            int o = vcol[t];
            sh_o32[tid] = o * 32;
            const float4* lp = (const float4*)(g_l1 + (size_t)t * 8);
            const float4* ip = (const float4*)(g_invC + (size_t)o * 8);
            float4 a = lp[0], b = lp[1], ia = ip[0], ib = ip[1];
            float4* sl = (float4*)&sh_l[tid][0];
            sl[0] = make_float4(a.x*ia.x, a.y*ia.y, a.z*ia.z, a.w*ia.w);
            sl[1] = make_float4(b.x*ib.x, b.y*ib.y, b.z*ib.z, b.w*ib.w);
        }
        __syncthreads();
        int i = 0;
        for (; i + 1 < n; i += 2) {
            int q0 = sh_o32[i], q1 = sh_o32[i+1];
            float4 u0 = *(const float4*)&sh_l[i][0];
            float4 v0 = *(const float4*)&sh_l[i][4];
            float4 u1 = *(const float4*)&sh_l[i+1][0];
            float4 v1 = *(const float4*)&sh_l[i+1][4];
            if (w == 0) {
                float2 A0 = __ldg(&W2p[q0     + lane]);
                float2 B0 = __ldg(&W2p[q0*2   + lane]);
                float2 C0 = __ldg(&W2p[q0*3   + lane]);
                float2 D0 = __ldg(&W2p[q0*7   + lane]);
                float2 A1 = __ldg(&W2p[q1     + lane]);
                float2 B1 = __ldg(&W2p[q1*2   + lane]);
                float2 C1 = __ldg(&W2p[q1*3   + lane]);
                float2 D1 = __ldg(&W2p[q1*7   + lane]);
                acc0 += u0.x + u1.x;
                c0 = fmaf(u0.y, A0.x, c0); c1 = fmaf(u0.y, A0.y, c1);
                c0 = fmaf(u0.z, B0.x, c0); c1 = fmaf(u0.z, B0.y, c1);
                c0 = fmaf(u0.w, C0.x, c0); c1 = fmaf(u0.w, C0.y, c1);
                c0 = fmaf(v0.w, D0.x, c0); c1 = fmaf(v0.w, D0.y, c1);
                c0 = fmaf(u1.y, A1.x, c0); c1 = fmaf(u1.y, A1.y, c1);
                c0 = fmaf(u1.z, B1.x, c0); c1 = fmaf(u1.z, B1.y, c1);
                c0 = fmaf(u1.w, C1.x, c0); c1 = fmaf(u1.w, C1.y, c1);
                c0 = fmaf(v1.w, D1.x, c0); c1 = fmaf(v1.w, D1.y, c1);
            } else {
                float2 A0 = __ldg(&W2p[q0*4   + lane]);
                float2 B0 = __ldg(&W2p[q0*5   + lane]);
                float2 C0 = __ldg(&W2p[q0*6   + lane]);
                float2 A1 = __ldg(&W2p[q1*4   + lane]);
                float2 B1 = __ldg(&W2p[q1*5   + lane]);
                float2 C1 = __ldg(&W2p[q1*6   + lane]);
                c0 = fmaf(v0.x, A0.x, c0); c1 = fmaf(v0.x, A0.y, c1);
                c0 = fmaf(v0.y, B0.x, c0); c1 = fmaf(v0.y, B0.y, c1);
                c0 = fmaf(v0.z, C0.x, c0); c1 = fmaf(v0.z, C0.y, c1);
                c0 = fmaf(v1.x, A1.x, c0); c1 = fmaf(v1.x, A1.y, c1);
                c0 = fmaf(v1.y, B1.x, c0); c1 = fmaf(v1.y, B1.y, c1);
                c0 = fmaf(v1.z, C1.x, c0); c1 = fmaf(v1.z, C1.y, c1);
            }
        }
        if (i < n) {
            int q0 = sh_o32[i];
            float4 u0 = *(const float4*)&sh_l[i][0];
            float4 v0 = *(const float4*)&sh_l[i][4];
            if (w == 0) {
                float2 A0 = __ldg(&W2p[q0     + lane]);
                float2 B0 = __ldg(&W2p[q0*2   + lane]);
                float2 C0 = __ldg(&W2p[q0*3   + lane]);
                float2 D0 = __ldg(&W2p[q0*7   + lane]);
                acc0 += u0.x;
                c0 = fmaf(u0.y, A0.x, c0); c1 = fmaf(u0.y, A0.y, c1);
                c0 = fmaf(u0.z, B0.x, c0); c1 = fmaf(u0.z, B0.y, c1);
                c0 = fmaf(u0.w, C0.x, c0); c1 = fmaf(u0.w, C0.y, c1);
                c0 = fmaf(v0.w, D0.x, c0); c1 = fmaf(v0.w, D0.y, c1);
            } else {
                float2 A0 = __ldg(&W2p[q0*4   + lane]);
                float2 B0 = __ldg(&W2p[q0*5   + lane]);
                float2 C0 = __ldg(&W2p[q0*6   + lane]);
                c0 = fmaf(v0.x, A0.x, c0); c1 = fmaf(v0.x, A0.y, c1);
                c0 = fmaf(v0.y, B0.x, c0); c1 = fmaf(v0.y, B0.y, c1);
                c0 = fmaf(v0.z, C0.x, c0); c1 = fmaf(v0.z, C0.y, c1);
            }
        }
        __syncthreads();
    }

    __shared__ float sred[2][64];
    __shared__ float s0;
    sred[w][lane*2] = c0; sred[w][lane*2 + 1] = c1;
    if (tid == 0) s0 = acc0;
    __syncthreads();
    float acc = sred[0][tid] + sred[1][tid] + s0 * __ldg(&W1[tid]);
    g_h[(size_t)s*64 + tid] = fmaxf(acc + bias1[tid], 0.f);
}

// ---------------- K65: H2[o][r*16+c] = h[o] @ W2[r]  (profiled slot) --------
// 625 blocks x 128 threads; 32 nodes per block; W2 staged in shared once.
#define K65_NB 32
__global__ __launch_bounds__(128) void k65_h2(const float* __restrict__ W2) {
    __shared__ float sW2[64*128];                // sW2[hh*128 + j], j = r*16+c
    __shared__ __align__(16) float sh_h[K65_NB][64];
    int tid = threadIdx.x;
    int nb = blockIdx.x * K65_NB;

    // stage W2 transposed-to-cat layout: sW2[hh][j] = W2[(j>>4)*1024 + hh*16 + (j&15)]
    for (int idx = tid; idx < 64*128; idx += 128) {
        int hh = idx >> 7, j = idx & 127;
        sW2[idx] = __ldg(&W2[(j >> 4) * 1024 + hh * 16 + (j & 15)]);
    }
    // stage 32 nodes' h rows (coalesced float4)
    {
        const float4* hp = (const float4*)(g_h + (size_t)nb * 64);
        float4* sp = (float4*)&sh_h[0][0];
        for (int idx = tid; idx < K65_NB * 16; idx += 128) sp[idx] = hp[idx];
    }
    __syncthreads();

    float y[K65_NB];
#pragma unroll
    for (int n = 0; n < K65_NB; n++) y[n] = 0.f;

    for (int hh = 0; hh < 64; hh += 4) {
        float w0 = sW2[(hh+0)*128 + tid];
        float w1 = sW2[(hh+1)*128 + tid];
        float w2 = sW2[(hh+2)*128 + tid];
        float w3 = sW2[(hh+3)*128 + tid];
#pragma unroll
        for (int n = 0; n < K65_NB; n++) {
            float4 hv = *(const float4*)&sh_h[n][hh];
            y[n] = fmaf(hv.x, w0, fmaf(hv.y, w1, fmaf(hv.z, w2, fmaf(hv.w, w3, y[n]))));
        }
    }
#pragma unroll
    for (int n = 0; n < K65_NB; n++)
        g_h2[(size_t)(nb + n) * 128 + tid] = y[n];
}

// ---------------- K7: h2-gather via H2; thread = (p, c) ---------------------
__global__ __launch_bounds__(128) void k7_logits(
    const int* __restrict__ vcol, float* __restrict__ out)
{
    int s = blockIdx.x, tid = threadIdx.x;
    int beg = g_off_s[s], end = g_off_s[s+1];
    if (beg == end) return;
    int p = tid >> 4, c = tid & 15;
    int q = s * p;
    int r = q / NNODES;
    int n_ = q - r * NNODES;
    int h2off = r * 16 + c;                      // column within H2 row

    __shared__ __align__(16) float sh_l[128][8];
    __shared__ int sh_o[128];
    float y = 0.f;
    const float4* ir = (const float4*)(g_invR + (size_t)s * 8);
    float4 ia = ir[0], ib = ir[1];

    for (int tile = beg; tile < end; tile += 128) {
        int n = min(128, end - tile);
        if (tid < n) {
            int t = g_perm_s[tile + tid];
            sh_o[tid] = vcol[t];
            const float4* lp = (const float4*)(g_l2 + (size_t)t * 8);
            float4 la = lp[0], lb = lp[1];
            float4* sl = (float4*)&sh_l[tid][0];
            sl[0] = make_float4(la.x*ia.x, la.y*ia.y, la.z*ia.z, la.w*ia.w);
            sl[1] = make_float4(lb.x*ib.x, lb.y*ib.y, lb.z*ib.z, lb.w*ib.w);
        }
        __syncthreads();
        int i = 0;
        for (; i + 1 < n; i += 2) {
            float lv0 = sh_l[i][p];
            float lv1 = sh_l[i+1][p];
            float hv0 = __ldg(&g_h2[(size_t)sh_o[i]  *128 + h2off]);
            float hv1 = __ldg(&g_h2[(size_t)sh_o[i+1]*128 + h2off]);
            y = fmaf(lv0, hv0, y);
            y = fmaf(lv1, hv1, y);
        }
        if (i < n) {
            y = fmaf(sh_l[i][p], __ldg(&g_h2[(size_t)sh_o[i]*128 + h2off]), y);
        }
        __syncthreads();
    }

    if (p == 0) {
        atomicAdd(&g_out0[(s & 63)*16 + c], y);
    } else {
        atomicAdd(&out[n_*NC + c], y);
    }
}

// ---------------- K8: fold striped p=0 partials + zero g_out0 for next call -
__global__ void k8_reduce(float* __restrict__ out) {
    int c = threadIdx.x;
    if (c >= 16) return;
    float sum = 0.f;
#pragma unroll
    for (int k = 0; k < 64; k++) sum += g_out0[k*16 + c];
    out[c] += sum;
#pragma unroll
    for (int k = 0; k < 64; k++) g_out0[k*16 + c] = 0.f;
}

// ---------------- launch ----------------------------------------------------
extern "C" void kernel_launch(void* const* d_in, const int* in_sizes, int n_in,
                              void* d_out, int out_size) {
    const float* rm    = (const float*)d_in[0];
    const int*   hrow  = (const int*)  d_in[1];
    const int*   vcol  = (const int*)  d_in[4];
    const float* Wl1   = (const float*)d_in[5];
    const float* bl1   = (const float*)d_in[6];
    const float* Wl2   = (const float*)d_in[7];
    const float* bl2   = (const float*)d_in[8];
    const float* W1    = (const float*)d_in[9];
    const float* W2    = (const float*)d_in[10];
    const float* bias1 = (const float*)d_in[11];
    const float* bias2 = (const float*)d_in[12];
    float* out = (float*)d_out;

    k1_l1l2         <<<(NT + 255) / 256, 256>>>(rm, Wl1, bl1, Wl2, bl2, hrow, vcol); // 1st
    k34_scan_scatter<<<148, 1024>>>(hrow, out, bias2);                               // 2nd
    k6_h            <<<NNODES, 64>>>(vcol, W1, bias1);                               // 3rd
    k65_h2          <<<NNODES / K65_NB, 128>>>(W2);                                  // 4th <- profiled
    k7_logits       <<<NNODES, 128>>>(vcol, out);                                    // 5th
    k8_reduce       <<<1, 16>>>(out);                                                // 6th
}

// round 14
// speedup vs baseline: 1.1082x; 1.0056x over previous
#include <cuda_runtime.h>

#define NT      250000
#define NNODES  20000
#define EMB     64
#define NC      16
#define NRP     (NNODES*8)

// ---------------- scratch (statically zero-initialized at module load) ------
__device__ __align__(16) float g_l1[NT*8];       // raw l1
__device__ __align__(16) float g_l2[NT*8];       // softmaxed l2
__device__ float g_colsum[NRP];
__device__ float g_rowsum[NRP];
__device__ __align__(16) float g_invC[NRP];      // [o][p] = 1/colsum[o*p]
__device__ __align__(16) float g_invR[NRP];      // [s][p] = 1/max(rowsum[s*p],1e-6)
__device__ __align__(16) float g_h[NNODES*EMB];
__device__ __align__(16) float g_h2[NNODES*128]; // H2[o][r*16+c] = h[o] @ W2[r]
__device__ int   g_cnt_s[NNODES];
__device__ int   g_off_s[NNODES+1];
__device__ int   g_cur_s[NNODES];
__device__ int   g_perm_s[NT];
__device__ float g_out0[64*16];                  // striped partials for p=0 logits
__device__ int   g_flag;                         // scan-done flag for k34

// ---------------- K1: GEMMs + softmax + sums atomics + s-hist ----------------
__global__ __launch_bounds__(256) void k1_l1l2(
    const float* __restrict__ rm,
    const float* __restrict__ Wl1, const float* __restrict__ bl1,
    const float* __restrict__ Wl2, const float* __restrict__ bl2,
    const int* __restrict__ hrow, const int* __restrict__ vcol)
{
    __shared__ float4 sW14[128], sW24[128];
    __shared__ float sb1[8], sb2[8];
    int tid = threadIdx.x;
    if (tid < 128) { sW14[tid] = ((const float4*)Wl1)[tid]; sW24[tid] = ((const float4*)Wl2)[tid]; }
    if (tid < 8) { sb1[tid] = bl1[tid]; sb2[tid] = bl2[tid]; }
    __syncthreads();

    int row = blockIdx.x * 256 + tid;
    const float4* rm4 = (const float4*)rm;

    float a1[8], a2[8];
#pragma unroll
    for (int p = 0; p < 8; p++) { a1[p] = sb1[p]; a2[p] = sb2[p]; }

    if (row < NT) {
        for (int k4 = 0; k4 < 16; k4++) {
            float4 x = rm4[(size_t)row * 16 + k4];
#pragma unroll
            for (int j = 0; j < 4; j++) {
                int k = k4 * 4 + j;
                float4 w1lo = sW14[k*2], w1hi = sW14[k*2+1];
                float4 w2lo = sW24[k*2], w2hi = sW24[k*2+1];
                float xv = (j == 0) ? x.x : (j == 1) ? x.y : (j == 2) ? x.z : x.w;
                a1[0] = fmaf(xv, w1lo.x, a1[0]);
                a1[1] = fmaf(xv, w1lo.y, a1[1]);
                a1[2] = fmaf(xv, w1lo.z, a1[2]);
                a1[3] = fmaf(xv, w1lo.w, a1[3]);
                a1[4] = fmaf(xv, w1hi.x, a1[4]);
                a1[5] = fmaf(xv, w1hi.y, a1[5]);
                a1[6] = fmaf(xv, w1hi.z, a1[6]);
                a1[7] = fmaf(xv, w1hi.w, a1[7]);
                a2[0] = fmaf(xv, w2lo.x, a2[0]);
                a2[1] = fmaf(xv, w2lo.y, a2[1]);
                a2[2] = fmaf(xv, w2lo.z, a2[2]);
                a2[3] = fmaf(xv, w2lo.w, a2[3]);
                a2[4] = fmaf(xv, w2hi.x, a2[4]);
                a2[5] = fmaf(xv, w2hi.y, a2[5]);
                a2[6] = fmaf(xv, w2hi.z, a2[6]);
                a2[7] = fmaf(xv, w2hi.w, a2[7]);
            }
        }
    }

    float p0l1 = 0.f, p0l2 = 0.f;
    if (row < NT) {
        float m = a2[0];
#pragma unroll
        for (int p = 1; p < 8; p++) m = fmaxf(m, a2[p]);
        float e[8], ssum = 0.f;
#pragma unroll
        for (int p = 0; p < 8; p++) { e[p] = __expf(a2[p] - m); ssum += e[p]; }
        float inv = 1.f / ssum;
#pragma unroll
        for (int p = 0; p < 8; p++) e[p] *= inv;

        float4* d1 = (float4*)(g_l1 + (size_t)row * 8);
        float4* d2 = (float4*)(g_l2 + (size_t)row * 8);
        d1[0] = make_float4(a1[0], a1[1], a1[2], a1[3]);
        d1[1] = make_float4(a1[4], a1[5], a1[6], a1[7]);
        d2[0] = make_float4(e[0], e[1], e[2], e[3]);
        d2[1] = make_float4(e[4], e[5], e[6], e[7]);

        int o = vcol[row], s = hrow[row];
        p0l1 = a1[0];
        p0l2 = e[0];
#pragma unroll
        for (int p = 1; p < 8; p++) {
            atomicAdd(&g_colsum[o * p], a1[p]);
            atomicAdd(&g_rowsum[s * p], e[p]);
        }
        atomicAdd(&g_cnt_s[s], 1);      // zeroed by previous call's k6 (or static init)
    }

    int lane = tid & 31, wid = tid >> 5;
#pragma unroll
    for (int d = 16; d > 0; d >>= 1) {
        p0l1 += __shfl_down_sync(0xffffffffu, p0l1, d);
        p0l2 += __shfl_down_sync(0xffffffffu, p0l2, d);
    }
    __shared__ float red1[8], red2[8];
    if (lane == 0) { red1[wid] = p0l1; red2[wid] = p0l2; }
    __syncthreads();
    if (tid == 0) {
        float s1 = 0.f, s2 = 0.f;
#pragma unroll
        for (int w = 0; w < 8; w++) { s1 += red1[w]; s2 += red2[w]; }
        atomicAdd(&g_colsum[0], s1);
        atomicAdd(&g_rowsum[0], s2);
    }
}

// ---------------- K34: scan + spin + scatter + inv tables + out init --------
__global__ __launch_bounds__(1024) void k34_scan_scatter(
    const int* __restrict__ hrow,
    float* __restrict__ out, const float* __restrict__ bias2)
{
    int tid = threadIdx.x, bid = blockIdx.x;

    if (bid == 0) {
        const int CH = 20;
        int base = tid * CH;
        int loc[CH]; int sum = 0;
#pragma unroll
        for (int j = 0; j < CH; j++) {
            int idx = base + j;
            int v = (idx < NNODES) ? g_cnt_s[idx] : 0;
            loc[j] = v; sum += v;
        }
        int lane = tid & 31, wid = tid >> 5;
        int x = sum;
#pragma unroll
        for (int d = 1; d < 32; d <<= 1) {
            int y = __shfl_up_sync(0xffffffffu, x, d);
            if (lane >= d) x += y;
        }
        __shared__ int wsum[32];
        if (lane == 31) wsum[wid] = x;
        __syncthreads();
        if (wid == 0) {
            int w = wsum[lane];
#pragma unroll
            for (int d = 1; d < 32; d <<= 1) {
                int y = __shfl_up_sync(0xffffffffu, w, d);
                if (lane >= d) w += y;
            }
            wsum[lane] = w;
        }
        __syncthreads();
        int run = x - sum + (wid ? wsum[wid - 1] : 0);
#pragma unroll
        for (int j = 0; j < CH; j++) {
            int idx = base + j;
            if (idx < NNODES) { g_off_s[idx] = run; g_cur_s[idx] = run; run += loc[j]; }
        }
        if (tid == 1023) g_off_s[NNODES] = wsum[31];
        __syncthreads();
        __threadfence();
        if (tid == 0) atomicExch(&g_flag, 1);    // release
    } else {
        if (tid == 0) {
            while (atomicAdd(&g_flag, 0) == 0) __nanosleep(128);   // acquire
        }
        __syncthreads();
    }

    int i = bid * 1024 + tid;
    int stride = 148 * 1024;
    for (int t = i; t < NT; t += stride) {
        int p = atomicAdd(&g_cur_s[hrow[t]], 1);
        g_perm_s[p] = t;
    }
    for (int j = i; j < NRP; j += stride) {
        int node = j >> 3, p = j & 7;
        g_invC[j] = 1.f / g_colsum[node * p];
        g_invR[j] = 1.f / fmaxf(g_rowsum[node * p], 1e-6f);
    }
    for (int j = i; j < NNODES*NC; j += stride) out[j] = bias2[j & (NC-1)];
}

// ---------------- K6: h[s] = relu(bias1 + sum) + cleanup for next call ------
__global__ __launch_bounds__(64) void k6_h(
    const int* __restrict__ vcol, const float* __restrict__ W1,
    const float* __restrict__ bias1)
{
    int s = blockIdx.x;
    int tid = threadIdx.x, lane = tid & 31, w = tid >> 5;

    {   // self-cleaning for next call
        int gi = s * 64 + tid;
        if (gi < NRP) { g_colsum[gi] = 0.f; g_rowsum[gi] = 0.f; }
        if (gi < NNODES) g_cnt_s[gi] = 0;
        if (gi == 0) g_flag = 0;
    }

    int beg = g_off_s[s], end = g_off_s[s+1];
    __shared__ __align__(16) float sh_l[64][8];
    __shared__ int sh_o32[64];
    const float2* W2p = (const float2*)W1;
    float c0 = 0.f, c1 = 0.f;
    float acc0 = 0.f;

    for (int tile = beg; tile < end; tile += 64) {
        int n = min(64, end - tile);
        if (tid < n) {
            int t = g_perm_s[tile + tid];
            int o = vcol[t];
            sh_o32[tid] = o * 32;
            const float4* lp = (const float4*)(g_l1 + (size_t)t * 8);
            const float4* ip = (const float4*)(g_invC + (size_t)o * 8);
            float4 a = lp[0], b = lp[1], ia = ip[0], ib = ip[1];
            float4* sl = (float4*)&sh_l[tid][0];
            sl[0] = make_float4(a.x*ia.x, a.y*ia.y, a.z*ia.z, a.w*ia.w);
            sl[1] = make_float4(b.x*ib.x, b.y*ib.y, b.z*ib.z, b.w*ib.w);
        }
        __syncthreads();
        int i = 0;
        for (; i + 1 < n; i += 2) {
            int q0 = sh_o32[i], q1 = sh_o32[i+1];
            float4 u0 = *(const float4*)&sh_l[i][0];
            float4 v0 = *(const float4*)&sh_l[i][4];
            float4 u1 = *(const float4*)&sh_l[i+1][0];
            float4 v1 = *(const float4*)&sh_l[i+1][4];
            if (w == 0) {
                float2 A0 = __ldg(&W2p[q0     + lane]);
                float2 B0 = __ldg(&W2p[q0*2   + lane]);
                float2 C0 = __ldg(&W2p[q0*3   + lane]);
                float2 D0 = __ldg(&W2p[q0*7   + lane]);
                float2 A1 = __ldg(&W2p[q1     + lane]);
                float2 B1 = __ldg(&W2p[q1*2   + lane]);
                float2 C1 = __ldg(&W2p[q1*3   + lane]);
                float2 D1 = __ldg(&W2p[q1*7   + lane]);
                acc0 += u0.x + u1.x;
                c0 = fmaf(u0.y, A0.x, c0); c1 = fmaf(u0.y, A0.y, c1);
                c0 = fmaf(u0.z, B0.x, c0); c1 = fmaf(u0.z, B0.y, c1);
                c0 = fmaf(u0.w, C0.x, c0); c1 = fmaf(u0.w, C0.y, c1);
                c0 = fmaf(v0.w, D0.x, c0); c1 = fmaf(v0.w, D0.y, c1);
                c0 = fmaf(u1.y, A1.x, c0); c1 = fmaf(u1.y, A1.y, c1);
                c0 = fmaf(u1.z, B1.x, c0); c1 = fmaf(u1.z, B1.y, c1);
                c0 = fmaf(u1.w, C1.x, c0); c1 = fmaf(u1.w, C1.y, c1);
                c0 = fmaf(v1.w, D1.x, c0); c1 = fmaf(v1.w, D1.y, c1);
            } else {
                float2 A0 = __ldg(&W2p[q0*4   + lane]);
                float2 B0 = __ldg(&W2p[q0*5   + lane]);
                float2 C0 = __ldg(&W2p[q0*6   + lane]);
                float2 A1 = __ldg(&W2p[q1*4   + lane]);
                float2 B1 = __ldg(&W2p[q1*5   + lane]);
                float2 C1 = __ldg(&W2p[q1*6   + lane]);
                c0 = fmaf(v0.x, A0.x, c0); c1 = fmaf(v0.x, A0.y, c1);
                c0 = fmaf(v0.y, B0.x, c0); c1 = fmaf(v0.y, B0.y, c1);
                c0 = fmaf(v0.z, C0.x, c0); c1 = fmaf(v0.z, C0.y, c1);
                c0 = fmaf(v1.x, A1.x, c0); c1 = fmaf(v1.x, A1.y, c1);
                c0 = fmaf(v1.y, B1.x, c0); c1 = fmaf(v1.y, B1.y, c1);
                c0 = fmaf(v1.z, C1.x, c0); c1 = fmaf(v1.z, C1.y, c1);
            }
        }
        if (i < n) {
            int q0 = sh_o32[i];
            float4 u0 = *(const float4*)&sh_l[i][0];
            float4 v0 = *(const float4*)&sh_l[i][4];
            if (w == 0) {
                float2 A0 = __ldg(&W2p[q0     + lane]);
                float2 B0 = __ldg(&W2p[q0*2   + lane]);
                float2 C0 = __ldg(&W2p[q0*3   + lane]);
                float2 D0 = __ldg(&W2p[q0*7   + lane]);
                acc0 += u0.x;
                c0 = fmaf(u0.y, A0.x, c0); c1 = fmaf(u0.y, A0.y, c1);
                c0 = fmaf(u0.z, B0.x, c0); c1 = fmaf(u0.z, B0.y, c1);
                c0 = fmaf(u0.w, C0.x, c0); c1 = fmaf(u0.w, C0.y, c1);
                c0 = fmaf(v0.w, D0.x, c0); c1 = fmaf(v0.w, D0.y, c1);
            } else {
                float2 A0 = __ldg(&W2p[q0*4   + lane]);
                float2 B0 = __ldg(&W2p[q0*5   + lane]);
                float2 C0 = __ldg(&W2p[q0*6   + lane]);
                c0 = fmaf(v0.x, A0.x, c0); c1 = fmaf(v0.x, A0.y, c1);
                c0 = fmaf(v0.y, B0.x, c0); c1 = fmaf(v0.y, B0.y, c1);
                c0 = fmaf(v0.z, C0.x, c0); c1 = fmaf(v0.z, C0.y, c1);
            }
        }
        __syncthreads();
    }

    __shared__ float sred[2][64];
    __shared__ float s0;
    sred[w][lane*2] = c0; sred[w][lane*2 + 1] = c1;
    if (tid == 0) s0 = acc0;
    __syncthreads();
    float acc = sred[0][tid] + sred[1][tid] + s0 * __ldg(&W1[tid]);
    g_h[(size_t)s*64 + tid] = fmaxf(acc + bias1[tid], 0.f);
}

// ---------------- K65: H2[o][r*16+c] = h[o] @ W2[r]  (profiled slot) --------
// 625 blocks x 256 threads; 32 nodes per block split into two 16-node halves
// (one per 128-thread group) -> y[16] per thread, regs ~55, occ ~2x R13.
#define K65_NB 32
__global__ __launch_bounds__(256) void k65_h2(const float* __restrict__ W2) {
    __shared__ float sW2[64*128];                   // sW2[hh*128 + j], j = r*16+c
    __shared__ __align__(16) float4 sh_h4[K65_NB][16];  // [node][hh/4]
    int tid = threadIdx.x;
    int col = tid & 127;
    int half = tid >> 7;                            // 0: nodes 0-15, 1: nodes 16-31
    int nb = blockIdx.x * K65_NB;

    // stage W2 in cat layout: sW2[hh][j] = W2[(j>>4)*1024 + hh*16 + (j&15)]
    for (int idx = tid; idx < 64*128; idx += 256) {
        int hh = idx >> 7, j = idx & 127;
        sW2[idx] = __ldg(&W2[(j >> 4) * 1024 + hh * 16 + (j & 15)]);
    }
    // stage 32 nodes' h rows (coalesced float4)
    {
        const float4* hp = (const float4*)(g_h + (size_t)nb * 64);
        float4* sp = (float4*)sh_h4;
        for (int idx = tid; idx < K65_NB * 16; idx += 256) sp[idx] = hp[idx];
    }
    __syncthreads();

    float y[16];
#pragma unroll
    for (int n = 0; n < 16; n++) y[n] = 0.f;
    int nbase = half * 16;

    for (int hh4 = 0; hh4 < 16; hh4++) {
        float w0 = sW2[(hh4*4+0)*128 + col];
        float w1 = sW2[(hh4*4+1)*128 + col];
        float w2 = sW2[(hh4*4+2)*128 + col];
        float w3 = sW2[(hh4*4+3)*128 + col];
#pragma unroll
        for (int n = 0; n < 16; n++) {
            float4 hv = sh_h4[nbase + n][hh4];
            y[n] = fmaf(hv.x, w0, fmaf(hv.y, w1, fmaf(hv.z, w2, fmaf(hv.w, w3, y[n]))));
        }
    }
#pragma unroll
    for (int n = 0; n < 16; n++)
        g_h2[(size_t)(nb + nbase + n) * 128 + col] = y[n];
}

// ---------------- K7: h2-gather via H2; thread = (p, c) ---------------------
__global__ __launch_bounds__(128) void k7_logits(
    const int* __restrict__ vcol, float* __restrict__ out)
{
    int s = blockIdx.x, tid = threadIdx.x;
    int beg = g_off_s[s], end = g_off_s[s+1];
    if (beg == end) return;
    int p = tid >> 4, c = tid & 15;
    int q = s * p;
    int r = q / NNODES;
    int n_ = q - r * NNODES;
    int h2off = r * 16 + c;                      // column within H2 row

    __shared__ __align__(16) float sh_l[128][8];
    __shared__ int sh_o[128];
    float y = 0.f;
    const float4* ir = (const float4*)(g_invR + (size_t)s * 8);
    float4 ia = ir[0], ib = ir[1];

    for (int tile = beg; tile < end; tile += 128) {
        int n = min(128, end - tile);
        if (tid < n) {
            int t = g_perm_s[tile + tid];
            sh_o[tid] = vcol[t];
            const float4* lp = (const float4*)(g_l2 + (size_t)t * 8);
            float4 la = lp[0], lb = lp[1];
            float4* sl = (float4*)&sh_l[tid][0];
            sl[0] = make_float4(la.x*ia.x, la.y*ia.y, la.z*ia.z, la.w*ia.w);
            sl[1] = make_float4(lb.x*ib.x, lb.y*ib.y, lb.z*ib.z, lb.w*ib.w);
        }
        __syncthreads();
        int i = 0;
        for (; i + 1 < n; i += 2) {
            float lv0 = sh_l[i][p];
            float lv1 = sh_l[i+1][p];
            float hv0 = __ldg(&g_h2[(size_t)sh_o[i]  *128 + h2off]);
            float hv1 = __ldg(&g_h2[(size_t)sh_o[i+1]*128 + h2off]);
            y = fmaf(lv0, hv0, y);
            y = fmaf(lv1, hv1, y);
        }
        if (i < n) {
            y = fmaf(sh_l[i][p], __ldg(&g_h2[(size_t)sh_o[i]*128 + h2off]), y);
        }
        __syncthreads();
    }

    if (p == 0) {
        atomicAdd(&g_out0[(s & 63)*16 + c], y);
    } else {
        atomicAdd(&out[n_*NC + c], y);
    }
}

// ---------------- K8: fold striped p=0 partials + zero g_out0 for next call -
__global__ void k8_reduce(float* __restrict__ out) {
    int c = threadIdx.x;
    if (c >= 16) return;
    float sum = 0.f;
#pragma unroll
    for (int k = 0; k < 64; k++) sum += g_out0[k*16 + c];
    out[c] += sum;
#pragma unroll
    for (int k = 0; k < 64; k++) g_out0[k*16 + c] = 0.f;
}

// ---------------- launch ----------------------------------------------------
extern "C" void kernel_launch(void* const* d_in, const int* in_sizes, int n_in,
                              void* d_out, int out_size) {
    const float* rm    = (const float*)d_in[0];
    const int*   hrow  = (const int*)  d_in[1];
    const int*   vcol  = (const int*)  d_in[4];
    const float* Wl1   = (const float*)d_in[5];
    const float* bl1   = (const float*)d_in[6];
    const float* Wl2   = (const float*)d_in[7];
    const float* bl2   = (const float*)d_in[8];
    const float* W1    = (const float*)d_in[9];
    const float* W2    = (const float*)d_in[10];
    const float* bias1 = (const float*)d_in[11];
    const float* bias2 = (const float*)d_in[12];
    float* out = (float*)d_out;

    k1_l1l2         <<<(NT + 255) / 256, 256>>>(rm, Wl1, bl1, Wl2, bl2, hrow, vcol); // 1st
    k34_scan_scatter<<<148, 1024>>>(hrow, out, bias2);                               // 2nd
    k6_h            <<<NNODES, 64>>>(vcol, W1, bias1);                               // 3rd
    k65_h2          <<<NNODES / K65_NB, 256>>>(W2);                                  // 4th <- profiled
    k7_logits       <<<NNODES, 128>>>(vcol, out);                                    // 5th
    k8_reduce       <<<1, 16>>>(out);                                                // 6th
}